// round 15
// baseline (speedup 1.0000x reference)
#include <cuda_runtime.h>
#include <cuda_fp16.h>
#include <cstddef>

// ---------------- constants ----------------
#define BSZ   4
#define SEQ   256
#define DM    512
#define NH    8
#define TW    65          // window length
#define NWIN  1024        // BSZ*SEQ
#define NROWS 66560       // NWIN*TW
#define VOC   32000
#define DFFN  2048
#define DIN   1024        // ssm d_inner
#define DST   16          // ssm d_state
#define NUNIQ 1085
#define UPAD  1152        // padded unique rows (9*128)

// ---------------- device scratch ----------------
__device__ float g_emb [BSZ*SEQ*DM];
__device__ float g_ssmv[16*BSZ*DM];
__device__ float g_hst [2*BSZ*DIN*DST];
__device__ float g_sx  [BSZ*DM];
__device__ float g_xz  [BSZ*2*DIN];
__device__ float g_y   [BSZ*DIN];
__device__ float g_pwq [DM];
__device__ unsigned g_barcnt;
__device__ unsigned g_bargen;

__device__ float  g_U   [(size_t)UPAD*DM];
__device__ __half g_UN  [(size_t)UPAD*DM];
__device__ __half g_QKVU[(size_t)UPAD*1536];

__device__ float  g_X   [(size_t)NROWS*DM];    // residual stream (fp32)
__device__ __half g_XN  [(size_t)NROWS*DM];    // LN output (half)
__device__ __half g_wide[(size_t)NROWS*DFFN];  // FFN1 hidden (half)
__device__ __half g_O   [(size_t)NROWS*DM];    // attn out (half)
__device__ __half g_Ql  [(size_t)NWIN*DM];
__device__ __half g_Ol  [(size_t)NWIN*DM];
__device__ __half g_XL  [(size_t)NWIN*DM];
__device__ __half g_HL  [(size_t)NWIN*DFFN];
__device__ __half g_FL  [(size_t)NWIN*DM];
__device__ float  g_vq  [(size_t)NWIN*NH*DM];  // Wk^T q per (window, head)
__device__ float  g_sbar[(size_t)NWIN*NH*DM];  // softmax-mixed xn rows

// transposed half weights ([N,K] row-major)
__device__ __half g_wqkvT[2*1536*DM];
__device__ __half g_woT  [2*DM*DM];
__device__ __half g_w1T  [2*DFFN*DM];
__device__ __half g_w2T  [2*DM*DFFN];
__device__ __half g_embh [(size_t)VOC*DM];     // [V,K] half

// ---------------- device helpers ----------------
__device__ __forceinline__ float softplusf(float x){
    return (x > 20.f) ? x : log1pf(expf(x));
}
__device__ __forceinline__ float geluf(float x){
    float x3 = x*x*x;
    return 0.5f*x*(1.f + tanhf(0.7978845608028654f*(x + 0.044715f*x3)));
}
__device__ __forceinline__ float siluf(float z){
    return z / (1.f + expf(-z));
}
__device__ __forceinline__ void mma_f16(float* c, const unsigned* a, const unsigned* b){
    asm volatile("mma.sync.aligned.m16n8k16.row.col.f32.f16.f16.f32 "
        "{%0,%1,%2,%3}, {%4,%5,%6,%7}, {%8,%9}, {%0,%1,%2,%3};"
        : "+f"(c[0]), "+f"(c[1]), "+f"(c[2]), "+f"(c[3])
        : "r"(a[0]), "r"(a[1]), "r"(a[2]), "r"(a[3]), "r"(b[0]), "r"(b[1]));
}
__device__ __forceinline__ void ldsm4(unsigned& r0, unsigned& r1, unsigned& r2, unsigned& r3,
                                      unsigned addr){
    asm volatile("ldmatrix.sync.aligned.m8n8.x4.shared.b16 {%0,%1,%2,%3}, [%4];"
        : "=r"(r0), "=r"(r1), "=r"(r2), "=r"(r3) : "r"(addr));
}
__device__ __forceinline__ void cpa16(unsigned dst, const void* src){
    asm volatile("cp.async.cg.shared.global [%0], [%1], 16;" :: "r"(dst), "l"(src));
}
#define CP_COMMIT() asm volatile("cp.async.commit_group;")
#define CP_WAIT1()  asm volatile("cp.async.wait_group 1;")
#define CP_WAIT0()  asm volatile("cp.async.wait_group 0;")

// software grid barrier (all blocks resident: grid <= SM count)
__device__ __forceinline__ void gridbar(){
    __threadfence();
    __syncthreads();
    if (threadIdx.x == 0){
        unsigned gen = *(volatile unsigned*)&g_bargen;
        unsigned t = atomicAdd(&g_barcnt, 1u);
        if (t == gridDim.x - 1){
            g_barcnt = 0u;
            __threadfence();
            *(volatile unsigned*)&g_bargen = gen + 1u;
        } else {
            while (*(volatile unsigned*)&g_bargen == gen) __nanosleep(64);
        }
        __threadfence();
    }
    __syncthreads();
}

// gather source row for initial residual X[r] (same mapping as old build_x)
__device__ __forceinline__ const float* gatherX(int r){
    int w = r/TW, j = r - w*TW;
    int b = w >> 8, t = w & 255;
    if (j == 0){
        int k = (t >= 17) ? ((t-1) >> 4) : 0;
        return k ? (g_ssmv + ((size_t)k*BSZ + b)*DM) : nullptr;
    }
    int tt = t - 64 + j;
    return (tt >= 0) ? (g_emb + ((size_t)b*SEQ + tt)*DM) : nullptr;
}

// ---------------- init / embed / weight prep ----------------
__global__ void init_zero_kernel(){
    int i = blockIdx.x*256 + threadIdx.x;
    if (i < 2*BSZ*DIN*DST) g_hst[i] = 0.f;
    if (i < BSZ*DM)        g_ssmv[i] = 0.f;
    if (i == 0){ g_barcnt = 0u; g_bargen = 0u; }
}

__global__ void tohalf_kernel(const float* __restrict__ src,
                              __half* __restrict__ dst, int n){
    int i = blockIdx.x*256 + threadIdx.x;
    int stride = gridDim.x*256;
    for (; i < n; i += stride) dst[i] = __float2half_rn(src[i]);
}

// transpose [K,N] fp32 -> [N,K] half
__global__ void transpose_half_kernel(const float* __restrict__ src,
                                      __half* __restrict__ dst,
                                      int K, int N){
    __shared__ float t[32][33];
    int k0 = blockIdx.y*32, n0 = blockIdx.x*32;
    int x = threadIdx.x, y = threadIdx.y;      // block (32, 8)
    #pragma unroll
    for (int yy = y; yy < 32; yy += 8)
        t[yy][x] = src[(size_t)(k0+yy)*N + n0 + x];
    __syncthreads();
    #pragma unroll
    for (int yy = y; yy < 32; yy += 8)
        dst[(size_t)(n0+yy)*K + k0 + x] = __float2half_rn(t[x][yy]);
}

__global__ void build_emb_kernel(const int* __restrict__ ids,
                                 const float* __restrict__ table){
    int i = blockIdx.x;               // b*SEQ+t
    int id = ids[i];
    const float* src = table + (size_t)id*DM;
    float* dst = g_emb + (size_t)i*DM;
    for (int c = threadIdx.x; c < DM; c += 128) dst[c] = src[c];
}

__global__ void pwq_kernel(const float* __restrict__ wk,
                           const float* __restrict__ q){
    int d = threadIdx.x;              // 512 threads
    float s = 0.f;
    #pragma unroll
    for (int k = 0; k < 64; k++) s += wk[d*64 + k]*q[k];
    g_pwq[d] = s;
}

// ---------------- Phase A: single persistent kernel ----------------
// grid 128 x 256. Per step: [pool+xz0] bar dbh0 bar xup0 bar xz1 bar dbh1 bar xup1 bar
__global__ __launch_bounds__(256)
void phaseA_kernel(const float* __restrict__ ssm_win,
                   const float* __restrict__ ssm_wdt,
                   const float* __restrict__ ssm_bdt,
                   const float* __restrict__ ssm_wB,
                   const float* __restrict__ ssm_wC,
                   const float* __restrict__ ssm_Alog,
                   const float* __restrict__ ssm_D,
                   const float* __restrict__ ssm_wout){
    __shared__ float xs[DIN];
    __shared__ float sc[80];
    __shared__ float red4[4][65];
    __shared__ float red8[8][33];
    __shared__ float bsm[DST], csm[DST];
    __shared__ float sinv;

    int blk = blockIdx.x;              // 0..127
    int tid = threadIdx.x;             // 0..255
    int lane = tid & 31, wid = tid >> 5;
    int b  = blk & 3;
    int cb = blk >> 2;                 // 0..31

    for (int k = 1; k <= 15; k++){
        int t = 16*k, kprev = k - 1;
        // ---- P1: pool (recomputed per block) + xz layer 0 slice ----
        {
            const float* srow = g_ssmv + ((size_t)kprev*BSZ + b)*DM;
            for (int j = wid; j < TW; j += 8){
                const float* row = nullptr;
                if (j == 0) row = srow;
                else { int tt = t - 64 + j; if (tt >= 0) row = g_emb + ((size_t)b*SEQ + tt)*DM; }
                float s = 0.f;
                if (row) for (int d = lane; d < DM; d += 32) s += row[d]*g_pwq[d];
                for (int o = 16; o; o >>= 1) s += __shfl_xor_sync(0xffffffffu, s, o);
                if (lane == 0) sc[j] = s*0.125f;
            }
            __syncthreads();
            if (wid == 0){
                float v0 = sc[lane];
                float v1 = sc[lane + 32];
                float v2 = (lane == 0) ? sc[64] : -1e30f;
                float m = fmaxf(v0, fmaxf(v1, v2));
                for (int o = 16; o; o >>= 1) m = fmaxf(m, __shfl_xor_sync(0xffffffffu, m, o));
                float e0 = expf(v0 - m), e1 = expf(v1 - m);
                float e2 = (lane == 0) ? expf(v2 - m) : 0.f;
                float s = e0 + e1 + e2;
                for (int o = 16; o; o >>= 1) s += __shfl_xor_sync(0xffffffffu, s, o);
                sc[lane] = e0; sc[lane + 32] = e1;
                if (lane == 0){ sc[64] = e2; sinv = 1.f/s; }
            }
            __syncthreads();
            {
                int j0 = (t >= 63) ? 1 : (64 - t);
                for (int d = tid; d < DM; d += 256){
                    float acc = sc[0]*srow[d];
                    const float* ebase = g_emb + ((size_t)b*SEQ + (t - 64))*DM + d;
                    #pragma unroll 4
                    for (int j = j0; j < TW; j++)
                        acc += sc[j]*ebase[(size_t)j*DM];
                    float v = acc*sinv;
                    xs[d] = v;
                    if (cb == 0) g_sx[b*DM + d] = v;
                }
            }
            __syncthreads();
            {
                int cl = tid & 63, sg = tid >> 6;
                int c = cb*64 + cl;
                float s = 0.f;
                int d0 = sg*128;
                #pragma unroll 8
                for (int d = d0; d < d0 + 128; d++) s += xs[d]*ssm_win[(size_t)d*2048 + c];
                red4[sg][cl] = s;
                __syncthreads();
                if (tid < 64)
                    g_xz[b*2048 + cb*64 + tid] =
                        red4[0][tid] + red4[1][tid] + red4[2][tid] + red4[3][tid];
            }
        }
        gridbar();
        for (int l = 0; l < 2; l++){
            if (l == 1){
                // xz layer 1 (reads updated g_sx)
                for (int i = tid; i < DM; i += 256) xs[i] = g_sx[b*DM + i];
                __syncthreads();
                const float* win = ssm_win + (size_t)DM*2*DIN;
                int cl = tid & 63, sg = tid >> 6;
                int c = cb*64 + cl;
                float s = 0.f;
                int d0 = sg*128;
                #pragma unroll 8
                for (int d = d0; d < d0 + 128; d++) s += xs[d]*win[(size_t)d*2048 + c];
                red4[sg][cl] = s;
                __syncthreads();
                if (tid < 64)
                    g_xz[b*2048 + cb*64 + tid] =
                        red4[0][tid] + red4[1][tid] + red4[2][tid] + red4[3][tid];
                gridbar();
            }
            // dbh: blocks 0..63 (16 col-blocks x 4 b)
            if (blk < 64){
                int cb2 = blk >> 2, bb = blk & 3;
                for (int i = tid; i < DIN; i += 256) xs[i] = g_xz[bb*2048 + i];
                __syncthreads();
                int cl = tid & 63, sg = tid >> 6;
                int c = cb2*64 + cl;
                {
                    float s = (sg == 0) ? ssm_bdt[(size_t)l*DIN + c] : 0.f;
                    const float* wdt = ssm_wdt + (size_t)l*DIN*DIN;
                    int d0 = sg*256;
                    #pragma unroll 8
                    for (int d = d0; d < d0 + 256; d++) s += xs[d]*wdt[(size_t)d*DIN + c];
                    red4[sg][cl] = s;
                }
                {
                    int o = tid & 31, seg = tid >> 5;
                    const float* w = (o < 16) ? (ssm_wB + (size_t)l*DIN*DST)
                                              : (ssm_wC + (size_t)l*DIN*DST);
                    int si = o & 15;
                    float p = 0.f;
                    int e0 = seg*128;
                    #pragma unroll 4
                    for (int d = e0; d < e0 + 128; d++) p += xs[d]*w[d*DST + si];
                    red8[seg][o] = p;
                }
                __syncthreads();
                if (tid < 32){
                    float tt = 0.f;
                    #pragma unroll
                    for (int q = 0; q < 8; q++) tt += red8[q][tid];
                    if (tid < 16) bsm[tid] = tt; else csm[tid - 16] = tt;
                }
                __syncthreads();
                if (tid < 64){
                    float dt = softplusf(red4[0][tid] + red4[1][tid] + red4[2][tid] + red4[3][tid]);
                    int cc = cb2*64 + tid;
                    float x1 = xs[cc];
                    float z  = g_xz[bb*2048 + DIN + cc];
                    const float* Alog = ssm_Alog + (size_t)l*DIN*DST;
                    const float* Dw   = ssm_D + (size_t)l*DIN;
                    float* hp = g_hst + (((size_t)l*BSZ + bb)*DIN + cc)*DST;
                    float y = 0.f;
                    #pragma unroll
                    for (int q = 0; q < DST; q++){
                        float Av = -expf(Alog[cc*DST + q]);
                        float hv = expf(dt*Av)*hp[q] + dt*bsm[q]*x1;
                        hp[q] = hv;
                        y += hv*csm[q];
                    }
                    y += Dw[cc]*x1;
                    y *= siluf(z);
                    g_y[bb*DIN + cc] = y;
                }
            }
            gridbar();
            // xup: blocks 0..63 (16 col-blocks x 4 b), 32 cols x 8 segs
            if (blk < 64){
                int cb2 = blk >> 2, bb = blk & 3;
                for (int i = tid; i < DIN; i += 256) xs[i] = g_y[bb*DIN + i];
                __syncthreads();
                int cl = tid & 31, sg = tid >> 5;
                int c = cb2*32 + cl;
                const float* wout = ssm_wout + (size_t)l*DIN*DM;
                float s = 0.f;
                int d0 = sg*128;
                #pragma unroll 8
                for (int d = d0; d < d0 + 128; d++) s += xs[d]*wout[(size_t)d*DM + c];
                red8[sg][cl] = s;
                __syncthreads();
                if (tid < 32){
                    float tt = 0.f;
                    #pragma unroll
                    for (int q = 0; q < 8; q++) tt += red8[q][tid];
                    int cc = cb2*32 + tid;
                    float nv = g_sx[bb*DM + cc] + tt;
                    g_sx[bb*DM + cc] = nv;
                    if (l == 1) g_ssmv[((size_t)k*BSZ + bb)*DM + cc] = nv;
                }
            }
            gridbar();
        }
    }
}

// ---------------- Phase B: batched transformer ----------------
__global__ void build_uniq_kernel(){
    int u = blockIdx.x;                // 0..UPAD-1
    float* dst = g_U + (size_t)u*DM;
    const float* src = nullptr;
    if (u >= 1 && u < 1025) src = g_emb + (size_t)(u-1)*DM;
    else if (u >= 1025 && u < NUNIQ){
        int idx = u - 1025; int k = idx/4 + 1, b = idx & 3;
        src = g_ssmv + ((size_t)k*BSZ + b)*DM;
    }
    for (int c = threadIdx.x; c < DM; c += 128) dst[c] = src ? src[c] : 0.f;
}

// LayerNorm; fp32 in (strided), half out
__global__ void ln_kernel(const float* __restrict__ in, long long ldi,
                          __half* __restrict__ out, long long ldo,
                          const float* __restrict__ gw,
                          const float* __restrict__ bw){
    long long r = blockIdx.x;
    const float* x = in + r*ldi;
    int tid = threadIdx.x;             // 256
    float v0 = x[tid], v1 = x[tid + 256];
    float s = v0 + v1, q = v0*v0 + v1*v1;
    __shared__ float ss[8], sq[8];
    for (int o = 16; o; o >>= 1){
        s += __shfl_xor_sync(0xffffffffu, s, o);
        q += __shfl_xor_sync(0xffffffffu, q, o);
    }
    if ((tid & 31) == 0){ ss[tid >> 5] = s; sq[tid >> 5] = q; }
    __syncthreads();
    if (tid < 8){
        s = ss[tid]; q = sq[tid];
        for (int o = 4; o; o >>= 1){
            s += __shfl_xor_sync(0xffu, s, o);
            q += __shfl_xor_sync(0xffu, q, o);
        }
        if (tid == 0){ ss[0] = s; sq[0] = q; }
    }
    __syncthreads();
    float mu  = ss[0]*(1.f/512.f);
    float var = sq[0]*(1.f/512.f) - mu*mu;
    float inv = rsqrtf(var + 1e-5f);
    __half* o = out + r*ldo;
    o[tid]       = __float2half_rn((v0 - mu)*inv*gw[tid] + bw[tid]);
    o[tid + 256] = __float2half_rn((v1 - mu)*inv*gw[tid + 256] + bw[tid + 256]);
}

// -------- pipelined fp16 tensor-core GEMM (m16n8k16 + ldmatrix) --------
#define LDHW 72            // halves per smem row (64 + 8 pad); 144 B
#define TILEH (128*LDHW)   // 9216 halves = 18432 B per tile

template<int ACT, bool RESID, bool HASBIAS, bool SWAPXY, bool OUTH, bool GX>
__global__ __launch_bounds__(128, 2)
void hgemm(const __half* __restrict__ A, long long lda,
           const __half* __restrict__ B, long long ldb,
           void* __restrict__ Cv, long long ldc,
           const float* __restrict__ bias, int K){
    extern __shared__ __half sh[];
    __half* As = sh;                 // [2][TILEH]
    __half* Bs = sh + 2*TILEH;       // [2][TILEH]

    long long bm = (long long)(SWAPXY ? blockIdx.x : blockIdx.y)*128;
    long long bn = (long long)(SWAPXY ? blockIdx.y : blockIdx.x)*128;
    int tid = threadIdx.x;
    int lane = tid & 31, wid = tid >> 5;
    int g = lane >> 2, r = lane & 3;
    int wm = (wid >> 1)*64, wn = (wid & 1)*64;

    int lrow = tid >> 3, lcc = tid & 7;
    const __half* Abase = A + (bm + lrow)*lda + lcc*8;
    const __half* Bbase = B + (bn + lrow)*ldb + lcc*8;
    unsigned aS = (unsigned)__cvta_generic_to_shared(As) + (lrow*144u + lcc*16u);
    unsigned bS = (unsigned)__cvta_generic_to_shared(Bs) + (lrow*144u + lcc*16u);

    int lr = lane & 15;
    unsigned kh = (unsigned)((lane >> 4)*16);
    unsigned aLm = (unsigned)__cvta_generic_to_shared(As) + (unsigned)((wm + lr)*144) + kh;
    unsigned bLm = (unsigned)__cvta_generic_to_shared(Bs) + (unsigned)((wn + lr)*144) + kh;

    float acc[4][8][4];
    #pragma unroll
    for (int i = 0; i < 4; i++)
        #pragma unroll
        for (int j = 0; j < 8; j++)
            #pragma unroll
            for (int q = 0; q < 4; q++) acc[i][j][q] = 0.f;

    int nkt = K >> 6;

    #pragma unroll
    for (int i = 0; i < 8; i++){
        cpa16(aS + i*16u*144u, Abase + (size_t)16*i*lda);
        cpa16(bS + i*16u*144u, Bbase + (size_t)16*i*ldb);
    }
    CP_COMMIT();

    for (int kt = 0; kt < nkt; kt++){
        int cur = kt & 1;
        if (kt + 1 < nkt){
            unsigned so = (cur ^ 1) ? (unsigned)(TILEH*2) : 0u;
            long long ko = (long long)(kt + 1)*64;
            #pragma unroll
            for (int i = 0; i < 8; i++){
                cpa16(aS + so + i*16u*144u, Abase + (size_t)16*i*lda + ko);
                cpa16(bS + so + i*16u*144u, Bbase + (size_t)16*i*ldb + ko);
            }
            CP_COMMIT();
            CP_WAIT1();
        } else {
            CP_WAIT0();
        }
        __syncthreads();

        unsigned coff = (unsigned)cur*(TILEH*2);
        #pragma unroll
        for (int ks = 0; ks < 4; ks++){
            unsigned kso = coff + (unsigned)ks*32u;
            unsigned af[4][4], bf[8][2];
            #pragma unroll
            for (int mt = 0; mt < 4; mt++)
                ldsm4(af[mt][0], af[mt][1], af[mt][2], af[mt][3],
                      aLm + kso + (unsigned)mt*2304u);
            #pragma unroll
            for (int p = 0; p < 4; p++)
                ldsm4(bf[2*p][0], bf[2*p+1][0], bf[2*p][1], bf[2*p+1][1],
                      bLm + kso + (unsigned)p*2304u);
            #pragma unroll
            for (int mt = 0; mt < 4; mt++)
                #pragma unroll
                for (int nt = 0; nt < 8; nt++)
                    mma_f16(acc[mt][nt], af[mt], bf[nt]);
        }
        __syncthreads();
    }

    #pragma unroll
    for (int mt = 0; mt < 4; mt++){
        const float* gx0 = nullptr;
        const float* gx1 = nullptr;
        if (GX){
            int rr0 = (int)(bm + wm) + mt*16 + g;
            gx0 = gatherX(rr0);
            gx1 = gatherX(rr0 + 8);
        }
        #pragma unroll
        for (int nt = 0; nt < 8; nt++){
            long long row0 = bm + wm + mt*16 + g;
            long long col  = bn + wn + nt*8 + r*2;
            float b0 = 0.f, b1 = 0.f;
            if (HASBIAS){ b0 = bias[col]; b1 = bias[col+1]; }
            float v00 = acc[mt][nt][0] + b0, v01 = acc[mt][nt][1] + b1;
            float v10 = acc[mt][nt][2] + b0, v11 = acc[mt][nt][3] + b1;
            if (ACT == 1){ v00 = geluf(v00); v01 = geluf(v01);
                           v10 = geluf(v10); v11 = geluf(v11); }
            if (GX){
                if (gx0){ v00 += gx0[col]; v01 += gx0[col+1]; }
                if (gx1){ v10 += gx1[col]; v11 += gx1[col+1]; }
            }
            if (OUTH){
                __half* C = (__half*)Cv;
                *(__half2*)(C + row0*ldc + col)     = __floats2half2_rn(v00, v01);
                *(__half2*)(C + (row0+8)*ldc + col) = __floats2half2_rn(v10, v11);
            } else {
                float* C = (float*)Cv;
                float* c0 = C + row0*ldc + col;
                float* c1 = C + (row0+8)*ldc + col;
                if (RESID){
                    float2 r0 = *(float2*)c0, r1 = *(float2*)c1;
                    v00 += r0.x; v01 += r0.y; v10 += r1.x; v11 += r1.y;
                }
                *(float2*)c0 = make_float2(v00, v01);
                *(float2*)c1 = make_float2(v10, v11);
            }
        }
    }
}

// full causal attention (layer 0): per (window, head); half2 smem K/V.
__global__ __launch_bounds__(256)
void attn_full_kernel(const __half* __restrict__ QKVU, __half* __restrict__ O){
    int w = blockIdx.x, h = blockIdx.y;
    int b = w >> 8, t = w & 255;
    __shared__ __half2 Ksh[TW*33];
    __shared__ __half2 Vsh[TW*33];
    __shared__ float qs[8][64];
    __shared__ float ps[8][68];
    __shared__ int us[TW];
    int tid = threadIdx.x;
    int lane = tid & 31, wid = tid >> 5;
    if (tid < TW){
        int j = tid, u;
        if (j == 0){
            int k = (t >= 17) ? ((t-1) >> 4) : 0;
            u = k ? (1025 + (k-1)*4 + b) : 0;
        } else {
            int tt = t - 64 + j;
            u = (tt >= 0) ? (1 + b*256 + tt) : 0;
        }
        us[j] = u;
    }
    __syncthreads();
    for (int idx = tid; idx < TW*32; idx += 256){
        int j = idx >> 5, d2 = idx & 31;
        const __half* base = QKVU + (size_t)us[j]*1536 + h*64;
        Ksh[j*33 + d2] = ((const __half2*)(base + 512))[d2];
        Vsh[j*33 + d2] = ((const __half2*)(base + 1024))[d2];
    }
    __syncthreads();
    for (int j = wid; j < TW; j += 8){
        const __half* qb = QKVU + (size_t)us[j]*1536 + h*64;
        qs[wid][lane]      = __half2float(qb[lane]);
        qs[wid][lane + 32] = __half2float(qb[lane + 32]);
        __syncwarp();
        int nk = j + 1;
        float sv[3];
        float pmax = -1e30f;
        #pragma unroll
        for (int r = 0; r < 3; r++){
            int k = lane + r*32;
            float s = -1e30f;
            if (k < nk){
                s = 0.f;
                const __half2* kr = &Ksh[k*33];
                #pragma unroll
                for (int d2 = 0; d2 < 32; d2++){
                    float2 f = __half22float2(kr[d2]);
                    s += qs[wid][2*d2]*f.x + qs[wid][2*d2+1]*f.y;
                }
                s *= 0.125f;
            }
            sv[r] = s;
            pmax = fmaxf(pmax, s);
        }
        for (int o = 16; o; o >>= 1)
            pmax = fmaxf(pmax, __shfl_xor_sync(0xffffffffu, pmax, o));
        float psum = 0.f;
        #pragma unroll
        for (int r = 0; r < 3; r++){
            int k = lane + r*32;
            float e = (k < nk) ? expf(sv[r] - pmax) : 0.f;
            if (k < nk) ps[wid][k] = e;
            psum += e;
        }
        for (int o = 16; o; o >>= 1)
            psum += __shfl_xor_sync(0xffffffffu, psum, o);
        float inv = 1.f/psum;
        __syncwarp();
        {
            float a0 = 0.f, a1 = 0.f;
            for (int k = 0; k < nk; k++){
                float p = ps[wid][k];
                float2 f = __half22float2(Vsh[k*33 + lane]);
                a0 += p*f.x;
                a1 += p*f.y;
            }
            __half2* orow = (__half2*)(O + (size_t)(w*TW + j)*DM + h*64);
            orow[lane] = __floats2half2_rn(a0*inv, a1*inv);
        }
        __syncwarp();
    }
}

// ---- layer-1 attention, factored form ----
__global__ void vq_kernel(const float* __restrict__ wqkv1){
    int w = blockIdx.x;
    __shared__ float qs[DM];
    int tid = threadIdx.x;             // 256
    qs[tid]       = __half2float(g_Ql[(size_t)w*DM + tid]);
    qs[tid + 256] = __half2float(g_Ql[(size_t)w*DM + tid + 256]);
    __syncthreads();
    int h = tid >> 5, lane = tid & 31;
    const float* qh = qs + h*64;
    for (int d = lane; d < DM; d += 32){
        const float* wrow = wqkv1 + (size_t)d*1536 + 512 + h*64;
        float s = 0.f;
        #pragma unroll
        for (int c = 0; c < 64; c++) s += wrow[c]*qh[c];
        g_vq[((size_t)w*NH + h)*DM + d] = s;
    }
}

#define AMIX_SMEM (TW*DM*2 + NH*DM*4 + NH*68*4)
__global__ void attn_mix_kernel(){
    extern __shared__ char sm[];
    __half* xn = (__half*)sm;                        // [65][512]
    float* vsh = (float*)(sm + TW*DM*2);             // [8][512]
    float* sc  = vsh + NH*DM;                        // [8][68]
    int w = blockIdx.x;
    int tid = threadIdx.x;             // 256
    int lane = tid & 31, wid = tid >> 5;
    const uint4* src = (const uint4*)(g_XN + (size_t)w*TW*DM);
    for (int i = tid; i < TW*DM/8; i += 256) ((uint4*)xn)[i] = src[i];
    const float* vsrc = g_vq + (size_t)w*NH*DM;
    for (int i = tid; i < NH*DM; i += 256) vsh[i] = vsrc[i];
    __syncthreads();
    {
        int h = wid;
        const float* v = vsh + h*DM;
        for (int j = 0; j < TW; j++){
            const __half2* xr = (const __half2*)(xn + j*DM);
            float s = 0.f;
            #pragma unroll
            for (int i = lane; i < 256; i += 32){
                __half2 hv = xr[i];
                s += __low2float(hv)*v[2*i] + __high2float(hv)*v[2*i+1];
            }
            for (int o = 16; o; o >>= 1) s += __shfl_xor_sync(0xffffffffu, s, o);
            if (lane == 0) sc[h*68 + j] = s*0.125f;
        }
        __syncwarp();
        float v0 = sc[h*68 + lane];
        float v1 = sc[h*68 + lane + 32];
        float v2 = (lane == 0) ? sc[h*68 + 64] : -1e30f;
        float m = fmaxf(v0, fmaxf(v1, v2));
        for (int o = 16; o; o >>= 1) m = fmaxf(m, __shfl_xor_sync(0xffffffffu, m, o));
        float e0 = expf(v0 - m), e1 = expf(v1 - m);
        float e2 = (lane == 0) ? expf(v2 - m) : 0.f;
        float su = e0 + e1 + e2;
        for (int o = 16; o; o >>= 1) su += __shfl_xor_sync(0xffffffffu, su, o);
        float inv = 1.f/su;
        sc[h*68 + lane] = e0*inv;
        sc[h*68 + lane + 32] = e1*inv;
        if (lane == 0) sc[h*68 + 64] = e2*inv;
    }
    __syncthreads();
    float* outp = g_sbar + (size_t)w*NH*DM;
    #pragma unroll 1
    for (int h = 0; h < NH; h++){
        float a0 = 0.f, a1 = 0.f;
        const float* aw = sc + h*68;
        for (int j = 0; j < TW; j++){
            float a = aw[j];
            __half2 hv = *(const __half2*)(xn + j*DM + tid*2);
            a0 += a*__low2float(hv);
            a1 += a*__high2float(hv);
        }
        outp[h*DM + tid*2]     = a0;
        outp[h*DM + tid*2 + 1] = a1;
    }
}

__global__ void vo_kernel(const float* __restrict__ wqkv1){
    int w = blockIdx.x;
    __shared__ float sb[NH*DM];
    int tid = threadIdx.x;             // 256
    const float* ssrc = g_sbar + (size_t)w*NH*DM;
    for (int i = tid; i < NH*DM; i += 256) sb[i] = ssrc[i];
    __syncthreads();
    int c0 = tid, c1 = tid + 256;
    const float* s0 = sb + (c0 >> 6)*DM;
    const float* s1 = sb + (c1 >> 6)*DM;
    float a0 = 0.f, a1 = 0.f;
    for (int d = 0; d < DM; d++){
        const float* wr = wqkv1 + (size_t)d*1536 + 1024;
        a0 += s0[d]*wr[c0];
        a1 += s1[d]*wr[c1];
    }
    g_Ol[(size_t)w*DM + c0] = __float2half_rn(a0);
    g_Ol[(size_t)w*DM + c1] = __float2half_rn(a1);
}

// ---------------- host ----------------
template<int ACT, bool RESID, bool HASBIAS, bool SWAPXY, bool OUTH, bool GX>
static void launch_hgemm(dim3 grid, const __half* A, long long lda,
                         const __half* B, long long ldb,
                         void* C, long long ldc,
                         const float* bias, int K){
    int smem = 4*TILEH*2;       // 73728 B
    cudaFuncSetAttribute(hgemm<ACT,RESID,HASBIAS,SWAPXY,OUTH,GX>,
                         cudaFuncAttributeMaxDynamicSharedMemorySize, smem);
    hgemm<ACT,RESID,HASBIAS,SWAPXY,OUTH,GX><<<grid, 128, smem>>>(
        A, lda, B, ldb, C, ldc, bias, K);
}

extern "C" void kernel_launch(void* const* d_in, const int* in_sizes, int n_in,
                              void* d_out, int out_size){
    const int*   input_ids = (const int*)  d_in[0];
    const float* embedding = (const float*)d_in[1];
    const float* ln1_g = (const float*)d_in[2];
    const float* ln1_b = (const float*)d_in[3];
    const float* wqkv  = (const float*)d_in[4];
    const float* wo    = (const float*)d_in[5];
    const float* ln2_g = (const float*)d_in[6];
    const float* ln2_b = (const float*)d_in[7];
    const float* w1    = (const float*)d_in[8];
    const float* b1    = (const float*)d_in[9];
    const float* w2    = (const float*)d_in[10];
    const float* b2    = (const float*)d_in[11];
    const float* lnf_g = (const float*)d_in[12];
    const float* lnf_b = (const float*)d_in[13];
    const float* pool_q  = (const float*)d_in[14];
    const float* pool_wk = (const float*)d_in[15];
    const float* ssm_win = (const float*)d_in[16];
    const float* ssm_wdt = (const float*)d_in[17];
    const float* ssm_bdt = (const float*)d_in[18];
    const float* ssm_Alog= (const float*)d_in[19];
    const float* ssm_wB  = (const float*)d_in[20];
    const float* ssm_wC  = (const float*)d_in[21];
    const float* ssm_D   = (const float*)d_in[22];
    const float* ssm_wout= (const float*)d_in[23];
    float* out = (float*)d_out;

    float *pX, *pU;
    __half *pQKVU, *pUN, *pXN, *pW, *pO, *pQl, *pOl, *pXL, *pHL, *pFL;
    __half *pWqkvT, *pWoT, *pW1T, *pW2T, *pEmbH;
    cudaGetSymbolAddress((void**)&pX,  g_X);
    cudaGetSymbolAddress((void**)&pU,  g_U);
    cudaGetSymbolAddress((void**)&pQKVU, g_QKVU);
    cudaGetSymbolAddress((void**)&pUN, g_UN);
    cudaGetSymbolAddress((void**)&pXN, g_XN);
    cudaGetSymbolAddress((void**)&pW,  g_wide);
    cudaGetSymbolAddress((void**)&pO,  g_O);
    cudaGetSymbolAddress((void**)&pQl, g_Ql);
    cudaGetSymbolAddress((void**)&pOl, g_Ol);
    cudaGetSymbolAddress((void**)&pXL, g_XL);
    cudaGetSymbolAddress((void**)&pHL, g_HL);
    cudaGetSymbolAddress((void**)&pFL, g_FL);
    cudaGetSymbolAddress((void**)&pWqkvT, g_wqkvT);
    cudaGetSymbolAddress((void**)&pWoT, g_woT);
    cudaGetSymbolAddress((void**)&pW1T, g_w1T);
    cudaGetSymbolAddress((void**)&pW2T, g_w2T);
    cudaGetSymbolAddress((void**)&pEmbH, g_embh);

    init_zero_kernel<<<512, 256>>>();
    build_emb_kernel<<<BSZ*SEQ, 128>>>(input_ids, embedding);
    pwq_kernel<<<1, 512>>>(pool_wk, pool_q);

    // weight prep: transpose [K,N]->[N,K] half; embedding -> half
    dim3 tb(32, 8);
    for (int l = 0; l < 2; l++){
        transpose_half_kernel<<<dim3(1536/32, DM/32), tb>>>(
            wqkv + (size_t)l*DM*1536, pWqkvT + (size_t)l*1536*DM, DM, 1536);
        transpose_half_kernel<<<dim3(DM/32, DM/32), tb>>>(
            wo + (size_t)l*DM*DM, pWoT + (size_t)l*DM*DM, DM, DM);
        transpose_half_kernel<<<dim3(DFFN/32, DM/32), tb>>>(
            w1 + (size_t)l*DM*DFFN, pW1T + (size_t)l*DFFN*DM, DM, DFFN);
        transpose_half_kernel<<<dim3(DM/32, DFFN/32), tb>>>(
            w2 + (size_t)l*DFFN*DM, pW2T + (size_t)l*DM*DFFN, DFFN, DM);
    }
    tohalf_kernel<<<4096, 256>>>(embedding, pEmbH, VOC*DM);

    // ---- Phase A: single persistent kernel (15 steps, grid-wide barriers) ----
    phaseA_kernel<<<128, 256>>>(ssm_win, ssm_wdt, ssm_bdt, ssm_wB, ssm_wC,
                                ssm_Alog, ssm_D, ssm_wout);

    // ---- Phase B ----
    build_uniq_kernel<<<UPAD, 128>>>();
    ln_kernel<<<UPAD, 256>>>(pU, DM, pUN, DM, ln1_g, ln1_b);
    launch_hgemm<0,false,false,false,true,false>(dim3(1536/128, UPAD/128),
        pUN, DM, pWqkvT, DM, pQKVU, 1536, nullptr, DM);

    attn_full_kernel<<<dim3(NWIN, NH), 256>>>(pQKVU, pO);
    // WO GEMM with fused initial-residual gather (replaces build_x + RESID)
    launch_hgemm<0,false,false,false,false,true>(dim3(DM/128, NROWS/128),
        pO, DM, pWoT, DM, pX, DM, nullptr, DM);
    ln_kernel<<<NROWS, 256>>>(pX, DM, pXN, DM, ln2_g, ln2_b);
    launch_hgemm<1,false,true,false,true,false>(dim3(DFFN/128, NROWS/128),
        pXN, DM, pW1T, DM, pW, DFFN, b1, DM);
    launch_hgemm<0,true,true,false,false,false>(dim3(DM/128, NROWS/128),
        pW, DFFN, pW2T, DFFN, pX, DM, b2, DFFN);

    // layer 1: factored attention (last query only; no KV GEMM)
    const __half* wqkvT1 = pWqkvT + (size_t)1*1536*DM;
    const float*  wqkv1  = wqkv + (size_t)1*DM*1536;
    ln_kernel<<<NROWS, 256>>>(pX, DM, pXN, DM, ln1_g + DM, ln1_b + DM);
    launch_hgemm<0,false,false,false,true,false>(dim3(DM/128, NWIN/128),
        pXN + (size_t)64*DM, (long long)TW*DM, wqkvT1, DM, pQl, DM, nullptr, DM); // Q last
    vq_kernel<<<NWIN, 256>>>(wqkv1);
    cudaFuncSetAttribute(attn_mix_kernel,
                         cudaFuncAttributeMaxDynamicSharedMemorySize, AMIX_SMEM);
    attn_mix_kernel<<<NWIN, 256, AMIX_SMEM>>>();
    vo_kernel<<<NWIN, 256>>>(wqkv1);
    launch_hgemm<0,true,false,false,false,false>(dim3(DM/128, NWIN/128),
        pOl, DM, pWoT + (size_t)DM*DM, DM, pX + (size_t)64*DM, (long long)TW*DM,
        nullptr, DM);
    ln_kernel<<<NWIN, 256>>>(pX + (size_t)64*DM, (long long)TW*DM, pXL, DM,
                             ln2_g + DM, ln2_b + DM);
    launch_hgemm<1,false,true,false,true,false>(dim3(DFFN/128, NWIN/128),
        pXL, DM, pW1T + (size_t)DFFN*DM, DM, pHL, DFFN, b1 + DFFN, DM);
    launch_hgemm<0,true,true,false,false,false>(dim3(DM/128, NWIN/128),
        pHL, DFFN, pW2T + (size_t)DM*DFFN, DFFN, pX + (size_t)64*DM, (long long)TW*DM,
        b2 + DM, DFFN);

    // final LN (last rows) + tied logits
    ln_kernel<<<NWIN, 256>>>(pX + (size_t)64*DM, (long long)TW*DM, pFL, DM,
                             lnf_g, lnf_b);
    launch_hgemm<0,false,false,true,false,false>(dim3(NWIN/128, VOC/128),
        pFL, DM, pEmbH, DM, out, VOC, nullptr, DM);
}

// round 16
// speedup vs baseline: 1.5040x; 1.5040x over previous
#include <cuda_runtime.h>
#include <cuda_fp16.h>
#include <cstddef>

// ---------------- constants ----------------
#define BSZ   4
#define SEQ   256
#define DM    512
#define NH    8
#define TW    65          // window length
#define NWIN  1024        // BSZ*SEQ
#define NROWS 66560       // NWIN*TW
#define VOC   32000
#define DFFN  2048
#define DIN   1024        // ssm d_inner
#define DST   16          // ssm d_state
#define NUNIQ 1085
#define UPAD  1152        // padded unique rows (9*128)

// ---------------- device scratch ----------------
__device__ float g_emb [BSZ*SEQ*DM];
__device__ float g_ssmv[16*BSZ*DM];
__device__ float g_hst [2*BSZ*DIN*DST];
__device__ float g_sx  [BSZ*DM];
__device__ float g_xz  [BSZ*2*DIN];
__device__ float g_y   [BSZ*DIN];
__device__ float g_pwq [DM];

__device__ __half g_UN  [(size_t)UPAD*DM];
__device__ __half g_QKVU[(size_t)UPAD*1536];

__device__ float  g_X   [(size_t)NROWS*DM];    // residual stream (fp32)
__device__ __half g_XN  [(size_t)NROWS*DM];    // LN output (half)
__device__ __half g_wide[(size_t)NROWS*DFFN];  // FFN1 hidden (half)
__device__ __half g_O   [(size_t)NROWS*DM];    // attn out (half)
__device__ __half g_Ql  [(size_t)NWIN*DM];
__device__ __half g_Ol  [(size_t)NWIN*DM];
__device__ __half g_XL  [(size_t)NWIN*DM];
__device__ __half g_HL  [(size_t)NWIN*DFFN];
__device__ __half g_FL  [(size_t)NWIN*DM];
__device__ float  g_vq  [(size_t)NWIN*NH*DM];  // Wk^T q per (window, head)
__device__ float  g_sbar[(size_t)NWIN*NH*DM];  // softmax-mixed xn rows

// transposed half weights ([N,K] row-major)
__device__ __half g_wqkvT[2*1536*DM];
__device__ __half g_woT  [2*DM*DM];
__device__ __half g_w1T  [2*DFFN*DM];
__device__ __half g_w2T  [2*DM*DFFN];
__device__ __half g_embh [(size_t)VOC*DM];     // [V,K] half

// ---------------- device helpers ----------------
__device__ __forceinline__ float softplusf(float x){
    return (x > 20.f) ? x : log1pf(expf(x));
}
__device__ __forceinline__ float geluf(float x){
    float x3 = x*x*x;
    return 0.5f*x*(1.f + tanhf(0.7978845608028654f*(x + 0.044715f*x3)));
}
__device__ __forceinline__ float siluf(float z){
    return z / (1.f + expf(-z));
}
__device__ __forceinline__ void mma_f16(float* c, const unsigned* a, const unsigned* b){
    asm volatile("mma.sync.aligned.m16n8k16.row.col.f32.f16.f16.f32 "
        "{%0,%1,%2,%3}, {%4,%5,%6,%7}, {%8,%9}, {%0,%1,%2,%3};"
        : "+f"(c[0]), "+f"(c[1]), "+f"(c[2]), "+f"(c[3])
        : "r"(a[0]), "r"(a[1]), "r"(a[2]), "r"(a[3]), "r"(b[0]), "r"(b[1]));
}
__device__ __forceinline__ void ldsm4(unsigned& r0, unsigned& r1, unsigned& r2, unsigned& r3,
                                      unsigned addr){
    asm volatile("ldmatrix.sync.aligned.m8n8.x4.shared.b16 {%0,%1,%2,%3}, [%4];"
        : "=r"(r0), "=r"(r1), "=r"(r2), "=r"(r3) : "r"(addr));
}
__device__ __forceinline__ void cpa16(unsigned dst, const void* src){
    asm volatile("cp.async.cg.shared.global [%0], [%1], 16;" :: "r"(dst), "l"(src));
}
#define CP_COMMIT() asm volatile("cp.async.commit_group;")
#define CP_WAIT1()  asm volatile("cp.async.wait_group 1;")
#define CP_WAIT0()  asm volatile("cp.async.wait_group 0;")

// gather source row for initial residual X[r] (same mapping as old build_x)
__device__ __forceinline__ const float* gatherX(int r){
    int w = r/TW, j = r - w*TW;
    int b = w >> 8, t = w & 255;
    if (j == 0){
        int k = (t >= 17) ? ((t-1) >> 4) : 0;
        return k ? (g_ssmv + ((size_t)k*BSZ + b)*DM) : nullptr;
    }
    int tt = t - 64 + j;
    return (tt >= 0) ? (g_emb + ((size_t)b*SEQ + tt)*DM) : nullptr;
}

// unique-row source (same mapping as old build_uniq)
__device__ __forceinline__ const float* gatherU(int u){
    if (u >= 1 && u < 1025) return g_emb + (size_t)(u-1)*DM;
    if (u >= 1025 && u < NUNIQ){
        int idx = u - 1025; int k = idx/4 + 1, b = idx & 3;
        return g_ssmv + ((size_t)k*BSZ + b)*DM;
    }
    return nullptr;
}

// ---------------- init / embed / weight prep ----------------
__global__ void init_zero_kernel(){
    int i = blockIdx.x*256 + threadIdx.x;
    if (i < 2*BSZ*DIN*DST) g_hst[i] = 0.f;
    if (i < BSZ*DM)        g_ssmv[i] = 0.f;
}

__global__ void tohalf_kernel(const float* __restrict__ src,
                              __half* __restrict__ dst, int n){
    int i = blockIdx.x*256 + threadIdx.x;
    int stride = gridDim.x*256;
    for (; i < n; i += stride) dst[i] = __float2half_rn(src[i]);
}

// transpose [K,N] fp32 -> [N,K] half
__global__ void transpose_half_kernel(const float* __restrict__ src,
                                      __half* __restrict__ dst,
                                      int K, int N){
    __shared__ float t[32][33];
    int k0 = blockIdx.y*32, n0 = blockIdx.x*32;
    int x = threadIdx.x, y = threadIdx.y;      // block (32, 8)
    #pragma unroll
    for (int yy = y; yy < 32; yy += 8)
        t[yy][x] = src[(size_t)(k0+yy)*N + n0 + x];
    __syncthreads();
    #pragma unroll
    for (int yy = y; yy < 32; yy += 8)
        dst[(size_t)(n0+yy)*K + k0 + x] = __float2half_rn(t[x][yy]);
}

__global__ void build_emb_kernel(const int* __restrict__ ids,
                                 const float* __restrict__ table){
    int i = blockIdx.x;               // b*SEQ+t
    int id = ids[i];
    const float* src = table + (size_t)id*DM;
    float* dst = g_emb + (size_t)i*DM;
    for (int c = threadIdx.x; c < DM; c += 128) dst[c] = src[c];
}

__global__ void pwq_kernel(const float* __restrict__ wk,
                           const float* __restrict__ q){
    int d = threadIdx.x;              // 512 threads
    float s = 0.f;
    #pragma unroll
    for (int k = 0; k < 64; k++) s += wk[d*64 + k]*q[k];
    g_pwq[d] = s;
}

// ---------------- Phase A: pooling + SSM ----------------
// fused pool + layer-0 xz, split-K: grid (32, BSZ), 256 thr.
// Each block recomputes the pooled vector (cheap), block x==0 writes g_sx,
// then computes its 64-col x 4-seg slice of xz.
__global__ void xzpool_kernel(const float* __restrict__ win, int t, int kprev){
    __shared__ float sc[80];
    __shared__ float xs[DM];
    __shared__ float red4[4][65];
    __shared__ float sinv;
    int b = blockIdx.y;
    int tid = threadIdx.x;            // 256
    int lane = tid & 31, wid = tid >> 5;   // 8 warps
    const float* srow = g_ssmv + ((size_t)kprev*BSZ + b)*DM;
    for (int j = wid; j < TW; j += 8){
        const float* row = nullptr;
        if (j == 0) row = srow;
        else { int tt = t - 64 + j; if (tt >= 0) row = g_emb + ((size_t)b*SEQ + tt)*DM; }
        float s = 0.f;
        if (row) for (int d = lane; d < DM; d += 32) s += row[d]*g_pwq[d];
        for (int o = 16; o; o >>= 1) s += __shfl_xor_sync(0xffffffffu, s, o);
        if (lane == 0) sc[j] = s*0.125f;
    }
    __syncthreads();
    if (wid == 0){
        float v0 = sc[lane];
        float v1 = sc[lane + 32];
        float v2 = (lane == 0) ? sc[64] : -1e30f;
        float m = fmaxf(v0, fmaxf(v1, v2));
        for (int o = 16; o; o >>= 1) m = fmaxf(m, __shfl_xor_sync(0xffffffffu, m, o));
        float e0 = expf(v0 - m), e1 = expf(v1 - m);
        float e2 = (lane == 0) ? expf(v2 - m) : 0.f;
        float s = e0 + e1 + e2;
        for (int o = 16; o; o >>= 1) s += __shfl_xor_sync(0xffffffffu, s, o);
        sc[lane] = e0; sc[lane + 32] = e1;
        if (lane == 0){ sc[64] = e2; sinv = 1.f/s; }
    }
    __syncthreads();
    {
        int j0 = (t >= 63) ? 1 : (64 - t);
        for (int d = tid; d < DM; d += 256){
            float acc = sc[0]*srow[d];
            const float* ebase = g_emb + ((size_t)b*SEQ + (t - 64))*DM + d;
            #pragma unroll 4
            for (int j = j0; j < TW; j++)
                acc += sc[j]*ebase[(size_t)j*DM];
            float v = acc*sinv;
            xs[d] = v;
            if (blockIdx.x == 0) g_sx[b*DM + d] = v;
        }
    }
    __syncthreads();
    {
        int cl = tid & 63, sg = tid >> 6;
        int c = blockIdx.x*64 + cl;
        float s = 0.f;
        int d0 = sg*128;
        #pragma unroll 8
        for (int d = d0; d < d0 + 128; d++) s += xs[d]*win[(size_t)d*2048 + c];
        red4[sg][cl] = s;
        __syncthreads();
        if (tid < 64)
            g_xz[b*2048 + blockIdx.x*64 + tid] =
                red4[0][tid] + red4[1][tid] + red4[2][tid] + red4[3][tid];
    }
}

// xz matvec (layer 1), split-K: grid (32, BSZ), 256 thr = 64 cols x 4 K-segments
__global__ void ssm_xz_kernel(const float* __restrict__ win){
    __shared__ float xs[DM];
    __shared__ float red[4][65];
    int b = blockIdx.y;
    int tid = threadIdx.x;
    int cl = tid & 63, sg = tid >> 6;
    int c = blockIdx.x*64 + cl;                 // 0..2047
    for (int i = tid; i < DM; i += 256) xs[i] = g_sx[b*DM + i];
    __syncthreads();
    float s = 0.f;
    int d0 = sg*128;
    #pragma unroll 8
    for (int d = d0; d < d0 + 128; d++) s += xs[d]*win[(size_t)d*2048 + c];
    red[sg][cl] = s;
    __syncthreads();
    if (tid < 64){
        float t = red[0][tid] + red[1][tid] + red[2][tid] + red[3][tid];
        g_xz[b*2048 + blockIdx.x*64 + tid] = t;
    }
}

// fused dt + B/C projections + selective-scan update, split-K
// grid (16, BSZ), 256 thr = 64 cols x 4 K-segments (256 each)
__global__ void ssm_dbh_kernel(const float* __restrict__ wdt,
                               const float* __restrict__ bdt,
                               const float* __restrict__ wB,
                               const float* __restrict__ wC,
                               const float* __restrict__ Alog,
                               const float* __restrict__ Dw, int l){
    __shared__ float xs[DIN];
    __shared__ float red[4][65];
    __shared__ float redbc[8][33];
    __shared__ float bsm[DST], csm[DST];
    int b = blockIdx.y;
    int tid = threadIdx.x;
    int cl = tid & 63, sg = tid >> 6;
    int c = blockIdx.x*64 + cl;                 // 0..1023
    for (int i = tid; i < DIN; i += 256) xs[i] = g_xz[b*2048 + i];
    __syncthreads();
    // dt partial for own (col, segment)
    {
        float s = (sg == 0) ? bdt[c] : 0.f;
        int d0 = sg*256;
        #pragma unroll 8
        for (int d = d0; d < d0 + 256; d++) s += xs[d]*wdt[(size_t)d*DIN + c];
        red[sg][cl] = s;
    }
    // B/C projection partials (8 segs of 128)
    {
        int o = tid & 31, seg = tid >> 5;
        const float* w = (o < 16) ? wB : wC;
        int si = o & 15;
        float p = 0.f;
        int e0 = seg*128;
        #pragma unroll 4
        for (int d = e0; d < e0 + 128; d++) p += xs[d]*w[d*DST + si];
        redbc[seg][o] = p;
    }
    __syncthreads();
    if (tid < 32){
        float t = 0.f;
        #pragma unroll
        for (int q = 0; q < 8; q++) t += redbc[q][tid];
        if (tid < 16) bsm[tid] = t; else csm[tid - 16] = t;
    }
    __syncthreads();
    if (tid < 64){
        float dt = softplusf(red[0][tid] + red[1][tid] + red[2][tid] + red[3][tid]);
        int cc = blockIdx.x*64 + tid;
        float x1 = xs[cc];
        float z  = g_xz[b*2048 + DIN + cc];
        float* hp = g_hst + (((size_t)l*BSZ + b)*DIN + cc)*DST;
        float y = 0.f;
        #pragma unroll
        for (int q = 0; q < DST; q++){
            float Av = -expf(Alog[cc*DST + q]);
            float hv = expf(dt*Av)*hp[q] + dt*bsm[q]*x1;
            hp[q] = hv;
            y += hv*csm[q];
        }
        y += Dw[cc]*x1;
        y *= siluf(z);
        g_y[b*DIN + cc] = y;
    }
}

// xup matvec, split-K: grid (16, BSZ), 256 thr = 32 cols x 8 K-segments (128 each)
__global__ void ssm_xup_kernel(const float* __restrict__ wout, int k, int last){
    __shared__ float ys[DIN];
    __shared__ float red[8][33];
    int b = blockIdx.y;
    int tid = threadIdx.x;
    int cl = tid & 31, sg = tid >> 5;
    int c = blockIdx.x*32 + cl;                 // 0..511
    for (int i = tid; i < DIN; i += 256) ys[i] = g_y[b*DIN + i];
    __syncthreads();
    float s = 0.f;
    int d0 = sg*128;
    #pragma unroll 8
    for (int d = d0; d < d0 + 128; d++) s += ys[d]*wout[(size_t)d*DM + c];
    red[sg][cl] = s;
    __syncthreads();
    if (tid < 32){
        float t = 0.f;
        #pragma unroll
        for (int q = 0; q < 8; q++) t += red[q][tid];
        int cc = blockIdx.x*32 + tid;
        float nv = g_sx[b*DM + cc] + t;
        g_sx[b*DM + cc] = nv;
        if (last) g_ssmv[((size_t)k*BSZ + b)*DM + cc] = nv;
    }
}

// ---------------- Phase B: batched transformer ----------------
// LayerNorm; fp32 in (strided), half out
__global__ void ln_kernel(const float* __restrict__ in, long long ldi,
                          __half* __restrict__ out, long long ldo,
                          const float* __restrict__ gw,
                          const float* __restrict__ bw){
    long long r = blockIdx.x;
    const float* x = in + r*ldi;
    int tid = threadIdx.x;             // 256
    float v0 = x[tid], v1 = x[tid + 256];
    float s = v0 + v1, q = v0*v0 + v1*v1;
    __shared__ float ss[8], sq[8];
    for (int o = 16; o; o >>= 1){
        s += __shfl_xor_sync(0xffffffffu, s, o);
        q += __shfl_xor_sync(0xffffffffu, q, o);
    }
    if ((tid & 31) == 0){ ss[tid >> 5] = s; sq[tid >> 5] = q; }
    __syncthreads();
    if (tid < 8){
        s = ss[tid]; q = sq[tid];
        for (int o = 4; o; o >>= 1){
            s += __shfl_xor_sync(0xffu, s, o);
            q += __shfl_xor_sync(0xffu, q, o);
        }
        if (tid == 0){ ss[0] = s; sq[0] = q; }
    }
    __syncthreads();
    float mu  = ss[0]*(1.f/512.f);
    float var = sq[0]*(1.f/512.f) - mu*mu;
    float inv = rsqrtf(var + 1e-5f);
    __half* o = out + r*ldo;
    o[tid]       = __float2half_rn((v0 - mu)*inv*gw[tid] + bw[tid]);
    o[tid + 256] = __float2half_rn((v1 - mu)*inv*gw[tid + 256] + bw[tid + 256]);
}

// LN over gathered unique rows (replaces build_uniq + ln on g_U)
__global__ void ln_uniq_kernel(__half* __restrict__ out,
                               const float* __restrict__ gw,
                               const float* __restrict__ bw){
    int u = blockIdx.x;                // 0..UPAD-1
    const float* x = gatherU(u);
    int tid = threadIdx.x;             // 256
    float v0 = x ? x[tid] : 0.f;
    float v1 = x ? x[tid + 256] : 0.f;
    float s = v0 + v1, q = v0*v0 + v1*v1;
    __shared__ float ss[8], sq[8];
    for (int o = 16; o; o >>= 1){
        s += __shfl_xor_sync(0xffffffffu, s, o);
        q += __shfl_xor_sync(0xffffffffu, q, o);
    }
    if ((tid & 31) == 0){ ss[tid >> 5] = s; sq[tid >> 5] = q; }
    __syncthreads();
    if (tid < 8){
        s = ss[tid]; q = sq[tid];
        for (int o = 4; o; o >>= 1){
            s += __shfl_xor_sync(0xffu, s, o);
            q += __shfl_xor_sync(0xffu, q, o);
        }
        if (tid == 0){ ss[0] = s; sq[0] = q; }
    }
    __syncthreads();
    float mu  = ss[0]*(1.f/512.f);
    float var = sq[0]*(1.f/512.f) - mu*mu;
    float inv = rsqrtf(var + 1e-5f);
    __half* o = out + (size_t)u*DM;
    o[tid]       = __float2half_rn((v0 - mu)*inv*gw[tid] + bw[tid]);
    o[tid + 256] = __float2half_rn((v1 - mu)*inv*gw[tid + 256] + bw[tid + 256]);
}

// -------- pipelined fp16 tensor-core GEMM (m16n8k16 + ldmatrix) --------
#define LDHW 72            // halves per smem row (64 + 8 pad); 144 B
#define TILEH (128*LDHW)   // 9216 halves = 18432 B per tile

template<int ACT, bool RESID, bool HASBIAS, bool SWAPXY, bool OUTH, bool GX>
__global__ __launch_bounds__(128, 2)
void hgemm(const __half* __restrict__ A, long long lda,
           const __half* __restrict__ B, long long ldb,
           void* __restrict__ Cv, long long ldc,
           const float* __restrict__ bias, int K){
    extern __shared__ __half sh[];
    __half* As = sh;                 // [2][TILEH]
    __half* Bs = sh + 2*TILEH;       // [2][TILEH]

    long long bm = (long long)(SWAPXY ? blockIdx.x : blockIdx.y)*128;
    long long bn = (long long)(SWAPXY ? blockIdx.y : blockIdx.x)*128;
    int tid = threadIdx.x;
    int lane = tid & 31, wid = tid >> 5;
    int g = lane >> 2, r = lane & 3;
    int wm = (wid >> 1)*64, wn = (wid & 1)*64;

    int lrow = tid >> 3, lcc = tid & 7;
    const __half* Abase = A + (bm + lrow)*lda + lcc*8;
    const __half* Bbase = B + (bn + lrow)*ldb + lcc*8;
    unsigned aS = (unsigned)__cvta_generic_to_shared(As) + (lrow*144u + lcc*16u);
    unsigned bS = (unsigned)__cvta_generic_to_shared(Bs) + (lrow*144u + lcc*16u);

    int lr = lane & 15;
    unsigned kh = (unsigned)((lane >> 4)*16);
    unsigned aLm = (unsigned)__cvta_generic_to_shared(As) + (unsigned)((wm + lr)*144) + kh;
    unsigned bLm = (unsigned)__cvta_generic_to_shared(Bs) + (unsigned)((wn + lr)*144) + kh;

    float acc[4][8][4];
    #pragma unroll
    for (int i = 0; i < 4; i++)
        #pragma unroll
        for (int j = 0; j < 8; j++)
            #pragma unroll
            for (int q = 0; q < 4; q++) acc[i][j][q] = 0.f;

    int nkt = K >> 6;

    #pragma unroll
    for (int i = 0; i < 8; i++){
        cpa16(aS + i*16u*144u, Abase + (size_t)16*i*lda);
        cpa16(bS + i*16u*144u, Bbase + (size_t)16*i*ldb);
    }
    CP_COMMIT();

    for (int kt = 0; kt < nkt; kt++){
        int cur = kt & 1;
        if (kt + 1 < nkt){
            unsigned so = (cur ^ 1) ? (unsigned)(TILEH*2) : 0u;
            long long ko = (long long)(kt + 1)*64;
            #pragma unroll
            for (int i = 0; i < 8; i++){
                cpa16(aS + so + i*16u*144u, Abase + (size_t)16*i*lda + ko);
                cpa16(bS + so + i*16u*144u, Bbase + (size_t)16*i*ldb + ko);
            }
            CP_COMMIT();
            CP_WAIT1();
        } else {
            CP_WAIT0();
        }
        __syncthreads();

        unsigned coff = (unsigned)cur*(TILEH*2);
        #pragma unroll
        for (int ks = 0; ks < 4; ks++){
            unsigned kso = coff + (unsigned)ks*32u;
            unsigned af[4][4], bf[8][2];
            #pragma unroll
            for (int mt = 0; mt < 4; mt++)
                ldsm4(af[mt][0], af[mt][1], af[mt][2], af[mt][3],
                      aLm + kso + (unsigned)mt*2304u);
            #pragma unroll
            for (int p = 0; p < 4; p++)
                ldsm4(bf[2*p][0], bf[2*p+1][0], bf[2*p][1], bf[2*p+1][1],
                      bLm + kso + (unsigned)p*2304u);
            #pragma unroll
            for (int mt = 0; mt < 4; mt++)
                #pragma unroll
                for (int nt = 0; nt < 8; nt++)
                    mma_f16(acc[mt][nt], af[mt], bf[nt]);
        }
        __syncthreads();
    }

    #pragma unroll
    for (int mt = 0; mt < 4; mt++){
        const float* gx0 = nullptr;
        const float* gx1 = nullptr;
        if (GX){
            int rr0 = (int)(bm + wm) + mt*16 + g;
            gx0 = gatherX(rr0);
            gx1 = gatherX(rr0 + 8);
        }
        #pragma unroll
        for (int nt = 0; nt < 8; nt++){
            long long row0 = bm + wm + mt*16 + g;
            long long col  = bn + wn + nt*8 + r*2;
            float b0 = 0.f, b1 = 0.f;
            if (HASBIAS){ b0 = bias[col]; b1 = bias[col+1]; }
            float v00 = acc[mt][nt][0] + b0, v01 = acc[mt][nt][1] + b1;
            float v10 = acc[mt][nt][2] + b0, v11 = acc[mt][nt][3] + b1;
            if (ACT == 1){ v00 = geluf(v00); v01 = geluf(v01);
                           v10 = geluf(v10); v11 = geluf(v11); }
            if (GX){
                if (gx0){ v00 += gx0[col]; v01 += gx0[col+1]; }
                if (gx1){ v10 += gx1[col]; v11 += gx1[col+1]; }
            }
            if (OUTH){
                __half* C = (__half*)Cv;
                *(__half2*)(C + row0*ldc + col)     = __floats2half2_rn(v00, v01);
                *(__half2*)(C + (row0+8)*ldc + col) = __floats2half2_rn(v10, v11);
            } else {
                float* C = (float*)Cv;
                float* c0 = C + row0*ldc + col;
                float* c1 = C + (row0+8)*ldc + col;
                if (RESID){
                    float2 r0 = *(float2*)c0, r1 = *(float2*)c1;
                    v00 += r0.x; v01 += r0.y; v10 += r1.x; v11 += r1.y;
                }
                *(float2*)c0 = make_float2(v00, v01);
                *(float2*)c1 = make_float2(v10, v11);
            }
        }
    }
}

// full causal attention (layer 0): per (window, head); half2 smem K/V.
__global__ __launch_bounds__(256)
void attn_full_kernel(const __half* __restrict__ QKVU, __half* __restrict__ O){
    int w = blockIdx.x, h = blockIdx.y;
    int b = w >> 8, t = w & 255;
    __shared__ __half2 Ksh[TW*33];
    __shared__ __half2 Vsh[TW*33];
    __shared__ float qs[8][64];
    __shared__ float ps[8][68];
    __shared__ int us[TW];
    int tid = threadIdx.x;
    int lane = tid & 31, wid = tid >> 5;
    if (tid < TW){
        int j = tid, u;
        if (j == 0){
            int k = (t >= 17) ? ((t-1) >> 4) : 0;
            u = k ? (1025 + (k-1)*4 + b) : 0;
        } else {
            int tt = t - 64 + j;
            u = (tt >= 0) ? (1 + b*256 + tt) : 0;
        }
        us[j] = u;
    }
    __syncthreads();
    for (int idx = tid; idx < TW*32; idx += 256){
        int j = idx >> 5, d2 = idx & 31;
        const __half* base = QKVU + (size_t)us[j]*1536 + h*64;
        Ksh[j*33 + d2] = ((const __half2*)(base + 512))[d2];
        Vsh[j*33 + d2] = ((const __half2*)(base + 1024))[d2];
    }
    __syncthreads();
    for (int j = wid; j < TW; j += 8){
        const __half* qb = QKVU + (size_t)us[j]*1536 + h*64;
        qs[wid][lane]      = __half2float(qb[lane]);
        qs[wid][lane + 32] = __half2float(qb[lane + 32]);
        __syncwarp();
        int nk = j + 1;
        float sv[3];
        float pmax = -1e30f;
        #pragma unroll
        for (int r = 0; r < 3; r++){
            int k = lane + r*32;
            float s = -1e30f;
            if (k < nk){
                s = 0.f;
                const __half2* kr = &Ksh[k*33];
                #pragma unroll
                for (int d2 = 0; d2 < 32; d2++){
                    float2 f = __half22float2(kr[d2]);
                    s += qs[wid][2*d2]*f.x + qs[wid][2*d2+1]*f.y;
                }
                s *= 0.125f;
            }
            sv[r] = s;
            pmax = fmaxf(pmax, s);
        }
        for (int o = 16; o; o >>= 1)
            pmax = fmaxf(pmax, __shfl_xor_sync(0xffffffffu, pmax, o));
        float psum = 0.f;
        #pragma unroll
        for (int r = 0; r < 3; r++){
            int k = lane + r*32;
            float e = (k < nk) ? expf(sv[r] - pmax) : 0.f;
            if (k < nk) ps[wid][k] = e;
            psum += e;
        }
        for (int o = 16; o; o >>= 1)
            psum += __shfl_xor_sync(0xffffffffu, psum, o);
        float inv = 1.f/psum;
        __syncwarp();
        {
            float a0 = 0.f, a1 = 0.f;
            for (int k = 0; k < nk; k++){
                float p = ps[wid][k];
                float2 f = __half22float2(Vsh[k*33 + lane]);
                a0 += p*f.x;
                a1 += p*f.y;
            }
            __half2* orow = (__half2*)(O + (size_t)(w*TW + j)*DM + h*64);
            orow[lane] = __floats2half2_rn(a0*inv, a1*inv);
        }
        __syncwarp();
    }
}

// ---- layer-1 attention, factored form ----
__global__ void vq_kernel(const float* __restrict__ wqkv1){
    int w = blockIdx.x;
    __shared__ float qs[DM];
    int tid = threadIdx.x;             // 256
    qs[tid]       = __half2float(g_Ql[(size_t)w*DM + tid]);
    qs[tid + 256] = __half2float(g_Ql[(size_t)w*DM + tid + 256]);
    __syncthreads();
    int h = tid >> 5, lane = tid & 31;
    const float* qh = qs + h*64;
    for (int d = lane; d < DM; d += 32){
        const float* wrow = wqkv1 + (size_t)d*1536 + 512 + h*64;
        float s = 0.f;
        #pragma unroll
        for (int c = 0; c < 64; c++) s += wrow[c]*qh[c];
        g_vq[((size_t)w*NH + h)*DM + d] = s;
    }
}

#define AMIX_SMEM (TW*DM*2 + NH*DM*4 + NH*68*4)
__global__ void attn_mix_kernel(){
    extern __shared__ char sm[];
    __half* xn = (__half*)sm;                        // [65][512]
    float* vsh = (float*)(sm + TW*DM*2);             // [8][512]
    float* sc  = vsh + NH*DM;                        // [8][68]
    int w = blockIdx.x;
    int tid = threadIdx.x;             // 256
    int lane = tid & 31, wid = tid >> 5;
    const uint4* src = (const uint4*)(g_XN + (size_t)w*TW*DM);
    for (int i = tid; i < TW*DM/8; i += 256) ((uint4*)xn)[i] = src[i];
    const float* vsrc = g_vq + (size_t)w*NH*DM;
    for (int i = tid; i < NH*DM; i += 256) vsh[i] = vsrc[i];
    __syncthreads();
    {
        int h = wid;
        const float* v = vsh + h*DM;
        for (int j = 0; j < TW; j++){
            const __half2* xr = (const __half2*)(xn + j*DM);
            float s = 0.f;
            #pragma unroll
            for (int i = lane; i < 256; i += 32){
                __half2 hv = xr[i];
                s += __low2float(hv)*v[2*i] + __high2float(hv)*v[2*i+1];
            }
            for (int o = 16; o; o >>= 1) s += __shfl_xor_sync(0xffffffffu, s, o);
            if (lane == 0) sc[h*68 + j] = s*0.125f;
        }
        __syncwarp();
        float v0 = sc[h*68 + lane];
        float v1 = sc[h*68 + lane + 32];
        float v2 = (lane == 0) ? sc[h*68 + 64] : -1e30f;
        float m = fmaxf(v0, fmaxf(v1, v2));
        for (int o = 16; o; o >>= 1) m = fmaxf(m, __shfl_xor_sync(0xffffffffu, m, o));
        float e0 = expf(v0 - m), e1 = expf(v1 - m);
        float e2 = (lane == 0) ? expf(v2 - m) : 0.f;
        float su = e0 + e1 + e2;
        for (int o = 16; o; o >>= 1) su += __shfl_xor_sync(0xffffffffu, su, o);
        float inv = 1.f/su;
        sc[h*68 + lane] = e0*inv;
        sc[h*68 + lane + 32] = e1*inv;
        if (lane == 0) sc[h*68 + 64] = e2*inv;
    }
    __syncthreads();
    float* outp = g_sbar + (size_t)w*NH*DM;
    #pragma unroll 1
    for (int h = 0; h < NH; h++){
        float a0 = 0.f, a1 = 0.f;
        const float* aw = sc + h*68;
        for (int j = 0; j < TW; j++){
            float a = aw[j];
            __half2 hv = *(const __half2*)(xn + j*DM + tid*2);
            a0 += a*__low2float(hv);
            a1 += a*__high2float(hv);
        }
        outp[h*DM + tid*2]     = a0;
        outp[h*DM + tid*2 + 1] = a1;
    }
}

__global__ void vo_kernel(const float* __restrict__ wqkv1){
    int w = blockIdx.x;
    __shared__ float sb[NH*DM];
    int tid = threadIdx.x;             // 256
    const float* ssrc = g_sbar + (size_t)w*NH*DM;
    for (int i = tid; i < NH*DM; i += 256) sb[i] = ssrc[i];
    __syncthreads();
    int c0 = tid, c1 = tid + 256;
    const float* s0 = sb + (c0 >> 6)*DM;
    const float* s1 = sb + (c1 >> 6)*DM;
    float a0 = 0.f, a1 = 0.f;
    for (int d = 0; d < DM; d++){
        const float* wr = wqkv1 + (size_t)d*1536 + 1024;
        a0 += s0[d]*wr[c0];
        a1 += s1[d]*wr[c1];
    }
    g_Ol[(size_t)w*DM + c0] = __float2half_rn(a0);
    g_Ol[(size_t)w*DM + c1] = __float2half_rn(a1);
}

// ---------------- host ----------------
template<int ACT, bool RESID, bool HASBIAS, bool SWAPXY, bool OUTH, bool GX>
static void launch_hgemm(dim3 grid, const __half* A, long long lda,
                         const __half* B, long long ldb,
                         void* C, long long ldc,
                         const float* bias, int K){
    int smem = 4*TILEH*2;       // 73728 B
    cudaFuncSetAttribute(hgemm<ACT,RESID,HASBIAS,SWAPXY,OUTH,GX>,
                         cudaFuncAttributeMaxDynamicSharedMemorySize, smem);
    hgemm<ACT,RESID,HASBIAS,SWAPXY,OUTH,GX><<<grid, 128, smem>>>(
        A, lda, B, ldb, C, ldc, bias, K);
}

extern "C" void kernel_launch(void* const* d_in, const int* in_sizes, int n_in,
                              void* d_out, int out_size){
    const int*   input_ids = (const int*)  d_in[0];
    const float* embedding = (const float*)d_in[1];
    const float* ln1_g = (const float*)d_in[2];
    const float* ln1_b = (const float*)d_in[3];
    const float* wqkv  = (const float*)d_in[4];
    const float* wo    = (const float*)d_in[5];
    const float* ln2_g = (const float*)d_in[6];
    const float* ln2_b = (const float*)d_in[7];
    const float* w1    = (const float*)d_in[8];
    const float* b1    = (const float*)d_in[9];
    const float* w2    = (const float*)d_in[10];
    const float* b2    = (const float*)d_in[11];
    const float* lnf_g = (const float*)d_in[12];
    const float* lnf_b = (const float*)d_in[13];
    const float* pool_q  = (const float*)d_in[14];
    const float* pool_wk = (const float*)d_in[15];
    const float* ssm_win = (const float*)d_in[16];
    const float* ssm_wdt = (const float*)d_in[17];
    const float* ssm_bdt = (const float*)d_in[18];
    const float* ssm_Alog= (const float*)d_in[19];
    const float* ssm_wB  = (const float*)d_in[20];
    const float* ssm_wC  = (const float*)d_in[21];
    const float* ssm_D   = (const float*)d_in[22];
    const float* ssm_wout= (const float*)d_in[23];
    float* out = (float*)d_out;

    float *pX;
    __half *pQKVU, *pUN, *pXN, *pW, *pO, *pQl, *pOl, *pXL, *pHL, *pFL;
    __half *pWqkvT, *pWoT, *pW1T, *pW2T, *pEmbH;
    cudaGetSymbolAddress((void**)&pX,  g_X);
    cudaGetSymbolAddress((void**)&pQKVU, g_QKVU);
    cudaGetSymbolAddress((void**)&pUN, g_UN);
    cudaGetSymbolAddress((void**)&pXN, g_XN);
    cudaGetSymbolAddress((void**)&pW,  g_wide);
    cudaGetSymbolAddress((void**)&pO,  g_O);
    cudaGetSymbolAddress((void**)&pQl, g_Ql);
    cudaGetSymbolAddress((void**)&pOl, g_Ol);
    cudaGetSymbolAddress((void**)&pXL, g_XL);
    cudaGetSymbolAddress((void**)&pHL, g_HL);
    cudaGetSymbolAddress((void**)&pFL, g_FL);
    cudaGetSymbolAddress((void**)&pWqkvT, g_wqkvT);
    cudaGetSymbolAddress((void**)&pWoT, g_woT);
    cudaGetSymbolAddress((void**)&pW1T, g_w1T);
    cudaGetSymbolAddress((void**)&pW2T, g_w2T);
    cudaGetSymbolAddress((void**)&pEmbH, g_embh);

    init_zero_kernel<<<512, 256>>>();
    build_emb_kernel<<<BSZ*SEQ, 128>>>(input_ids, embedding);
    pwq_kernel<<<1, 512>>>(pool_wk, pool_q);

    // weight prep: transpose [K,N]->[N,K] half; embedding -> half
    dim3 tb(32, 8);
    for (int l = 0; l < 2; l++){
        transpose_half_kernel<<<dim3(1536/32, DM/32), tb>>>(
            wqkv + (size_t)l*DM*1536, pWqkvT + (size_t)l*1536*DM, DM, 1536);
        transpose_half_kernel<<<dim3(DM/32, DM/32), tb>>>(
            wo + (size_t)l*DM*DM, pWoT + (size_t)l*DM*DM, DM, DM);
        transpose_half_kernel<<<dim3(DFFN/32, DM/32), tb>>>(
            w1 + (size_t)l*DM*DFFN, pW1T + (size_t)l*DFFN*DM, DM, DFFN);
        transpose_half_kernel<<<dim3(DM/32, DFFN/32), tb>>>(
            w2 + (size_t)l*DFFN*DM, pW2T + (size_t)l*DM*DFFN, DFFN, DM);
    }
    tohalf_kernel<<<4096, 256>>>(embedding, pEmbH, VOC*DM);

    // ---- Phase A: 15 sequential SSM writes (split-K kernels) ----
    for (int k = 1; k <= 15; k++){
        int t = 16*k;
        for (int l = 0; l < 2; l++){
            if (l == 0)
                xzpool_kernel<<<dim3(32, BSZ), 256>>>(ssm_win, t, k-1);
            else
                ssm_xz_kernel<<<dim3(32, BSZ), 256>>>(ssm_win + (size_t)DM*2*DIN);
            ssm_dbh_kernel<<<dim3(16, BSZ), 256>>>(ssm_wdt + (size_t)l*DIN*DIN,
                                                   ssm_bdt + (size_t)l*DIN,
                                                   ssm_wB + (size_t)l*DIN*DST,
                                                   ssm_wC + (size_t)l*DIN*DST,
                                                   ssm_Alog + (size_t)l*DIN*DST,
                                                   ssm_D + (size_t)l*DIN, l);
            ssm_xup_kernel<<<dim3(16, BSZ), 256>>>(ssm_wout + (size_t)l*DIN*DM, k, l);
        }
    }

    // ---- Phase B ----
    ln_uniq_kernel<<<UPAD, 256>>>(pUN, ln1_g, ln1_b);
    launch_hgemm<0,false,false,false,true,false>(dim3(1536/128, UPAD/128),
        pUN, DM, pWqkvT, DM, pQKVU, 1536, nullptr, DM);

    attn_full_kernel<<<dim3(NWIN, NH), 256>>>(pQKVU, pO);
    // WO GEMM with fused initial-residual gather (replaces build_x + RESID)
    launch_hgemm<0,false,false,false,false,true>(dim3(DM/128, NROWS/128),
        pO, DM, pWoT, DM, pX, DM, nullptr, DM);
    ln_kernel<<<NROWS, 256>>>(pX, DM, pXN, DM, ln2_g, ln2_b);
    launch_hgemm<1,false,true,false,true,false>(dim3(DFFN/128, NROWS/128),
        pXN, DM, pW1T, DM, pW, DFFN, b1, DM);
    launch_hgemm<0,true,true,false,false,false>(dim3(DM/128, NROWS/128),
        pW, DFFN, pW2T, DFFN, pX, DM, b2, DFFN);

    // layer 1: factored attention (last query only; no KV GEMM)
    const __half* wqkvT1 = pWqkvT + (size_t)1*1536*DM;
    const float*  wqkv1  = wqkv + (size_t)1*DM*1536;
    ln_kernel<<<NROWS, 256>>>(pX, DM, pXN, DM, ln1_g + DM, ln1_b + DM);
    launch_hgemm<0,false,false,false,true,false>(dim3(DM/128, NWIN/128),
        pXN + (size_t)64*DM, (long long)TW*DM, wqkvT1, DM, pQl, DM, nullptr, DM); // Q last
    vq_kernel<<<NWIN, 256>>>(wqkv1);
    cudaFuncSetAttribute(attn_mix_kernel,
                         cudaFuncAttributeMaxDynamicSharedMemorySize, AMIX_SMEM);
    attn_mix_kernel<<<NWIN, 256, AMIX_SMEM>>>();
    vo_kernel<<<NWIN, 256>>>(wqkv1);
    launch_hgemm<0,true,false,false,false,false>(dim3(DM/128, NWIN/128),
        pOl, DM, pWoT + (size_t)DM*DM, DM, pX + (size_t)64*DM, (long long)TW*DM,
        nullptr, DM);
    ln_kernel<<<NWIN, 256>>>(pX + (size_t)64*DM, (long long)TW*DM, pXL, DM,
                             ln2_g + DM, ln2_b + DM);
    launch_hgemm<1,false,true,false,true,false>(dim3(DFFN/128, NWIN/128),
        pXL, DM, pW1T + (size_t)DFFN*DM, DM, pHL, DFFN, b1 + DFFN, DM);
    launch_hgemm<0,true,true,false,false,false>(dim3(DM/128, NWIN/128),
        pHL, DFFN, pW2T + (size_t)DM*DFFN, DFFN, pX + (size_t)64*DM, (long long)TW*DM,
        b2 + DM, DFFN);

    // final LN (last rows) + tied logits
    ln_kernel<<<NWIN, 256>>>(pX + (size_t)64*DM, (long long)TW*DM, pFL, DM,
                             lnf_g, lnf_b);
    launch_hgemm<0,false,false,true,false,false>(dim3(NWIN/128, VOC/128),
        pFL, DM, pEmbH, DM, out, VOC, nullptr, DM);
}

// round 17
// speedup vs baseline: 1.9403x; 1.2901x over previous
#include <cuda_runtime.h>
#include <cuda_fp16.h>
#include <cstddef>

// ---------------- constants ----------------
#define BSZ   4
#define SEQ   256
#define DM    512
#define NH    8
#define TW    65          // window length
#define NWIN  1024        // BSZ*SEQ
#define NROWS 66560       // NWIN*TW
#define VOC   32000
#define DFFN  2048
#define DIN   1024        // ssm d_inner
#define DST   16          // ssm d_state
#define NUNIQ 1085
#define UPAD  1152        // padded unique rows (9*128)

// ---------------- device scratch ----------------
__device__ float g_emb [BSZ*SEQ*DM];
__device__ float g_ssmv[16*BSZ*DM];
__device__ float g_hst [2*BSZ*DIN*DST];
__device__ float g_sx  [BSZ*DM];
__device__ float g_xz  [BSZ*2*DIN];
__device__ float g_y   [BSZ*DIN];
__device__ float g_pwq [DM];

__device__ __half g_UN  [(size_t)UPAD*DM];
__device__ __half g_QKVU[(size_t)UPAD*1536];

__device__ float  g_X   [(size_t)NROWS*DM];    // residual stream (fp32)
__device__ __half g_XN  [(size_t)NROWS*DM];    // LN output (half)
__device__ __half g_wide[(size_t)NROWS*DFFN];  // FFN1 hidden (half)
__device__ __half g_O   [(size_t)NROWS*DM];    // attn out (half)
__device__ __half g_XL  [(size_t)NWIN*DM];
__device__ __half g_HL  [(size_t)NWIN*DFFN];
__device__ __half g_FL  [(size_t)NWIN*DM];
__device__ __half g_vqH [(size_t)NWIN*NH*DM];  // xn_last @ M2^T  (half)
__device__ __half g_sbarH[(size_t)NWIN*NH*DM]; // softmax-mixed xn rows (half)

// transposed half weights ([N,K] row-major)
__device__ __half g_wqkvT[2*1536*DM];
__device__ __half g_woT  [2*DM*DM];
__device__ __half g_w1T  [2*DFFN*DM];
__device__ __half g_w2T  [2*DM*DFFN];
__device__ __half g_embh [(size_t)VOC*DM];     // [V,K] half
__device__ __half g_wqkvH1[(size_t)DM*1536];   // raw layer-1 wqkv, half
__device__ __half g_M2T [(size_t)NH*DM*DM];    // [h*512+d][e]
__device__ __half g_M3T [(size_t)DM*NH*DM];    // [e][h*512+d]

// ---------------- device helpers ----------------
__device__ __forceinline__ float softplusf(float x){
    return (x > 20.f) ? x : log1pf(expf(x));
}
__device__ __forceinline__ float geluf(float x){
    float x3 = x*x*x;
    return 0.5f*x*(1.f + tanhf(0.7978845608028654f*(x + 0.044715f*x3)));
}
__device__ __forceinline__ float siluf(float z){
    return z / (1.f + expf(-z));
}
__device__ __forceinline__ void mma_f16(float* c, const unsigned* a, const unsigned* b){
    asm volatile("mma.sync.aligned.m16n8k16.row.col.f32.f16.f16.f32 "
        "{%0,%1,%2,%3}, {%4,%5,%6,%7}, {%8,%9}, {%0,%1,%2,%3};"
        : "+f"(c[0]), "+f"(c[1]), "+f"(c[2]), "+f"(c[3])
        : "r"(a[0]), "r"(a[1]), "r"(a[2]), "r"(a[3]), "r"(b[0]), "r"(b[1]));
}
__device__ __forceinline__ void ldsm4(unsigned& r0, unsigned& r1, unsigned& r2, unsigned& r3,
                                      unsigned addr){
    asm volatile("ldmatrix.sync.aligned.m8n8.x4.shared.b16 {%0,%1,%2,%3}, [%4];"
        : "=r"(r0), "=r"(r1), "=r"(r2), "=r"(r3) : "r"(addr));
}
__device__ __forceinline__ void cpa16(unsigned dst, const void* src){
    asm volatile("cp.async.cg.shared.global [%0], [%1], 16;" :: "r"(dst), "l"(src));
}
#define CP_COMMIT() asm volatile("cp.async.commit_group;")
#define CP_WAIT1()  asm volatile("cp.async.wait_group 1;")
#define CP_WAIT0()  asm volatile("cp.async.wait_group 0;")

// gather source row for initial residual X[r] (same mapping as old build_x)
__device__ __forceinline__ const float* gatherX(int r){
    int w = r/TW, j = r - w*TW;
    int b = w >> 8, t = w & 255;
    if (j == 0){
        int k = (t >= 17) ? ((t-1) >> 4) : 0;
        return k ? (g_ssmv + ((size_t)k*BSZ + b)*DM) : nullptr;
    }
    int tt = t - 64 + j;
    return (tt >= 0) ? (g_emb + ((size_t)b*SEQ + tt)*DM) : nullptr;
}

// unique-row source (same mapping as old build_uniq)
__device__ __forceinline__ const float* gatherU(int u){
    if (u >= 1 && u < 1025) return g_emb + (size_t)(u-1)*DM;
    if (u >= 1025 && u < NUNIQ){
        int idx = u - 1025; int k = idx/4 + 1, b = idx & 3;
        return g_ssmv + ((size_t)k*BSZ + b)*DM;
    }
    return nullptr;
}

// ---------------- init / embed / weight prep ----------------
__global__ void init_zero_kernel(){
    int i = blockIdx.x*256 + threadIdx.x;
    if (i < 2*BSZ*DIN*DST) g_hst[i] = 0.f;
    if (i < BSZ*DM)        g_ssmv[i] = 0.f;
}

__global__ void tohalf_kernel(const float* __restrict__ src,
                              __half* __restrict__ dst, int n){
    int i = blockIdx.x*256 + threadIdx.x;
    int stride = gridDim.x*256;
    for (; i < n; i += stride) dst[i] = __float2half_rn(src[i]);
}

// transpose [K,N] fp32 -> [N,K] half
__global__ void transpose_half_kernel(const float* __restrict__ src,
                                      __half* __restrict__ dst,
                                      int K, int N){
    __shared__ float t[32][33];
    int k0 = blockIdx.y*32, n0 = blockIdx.x*32;
    int x = threadIdx.x, y = threadIdx.y;      // block (32, 8)
    #pragma unroll
    for (int yy = y; yy < 32; yy += 8)
        t[yy][x] = src[(size_t)(k0+yy)*N + n0 + x];
    __syncthreads();
    #pragma unroll
    for (int yy = y; yy < 32; yy += 8)
        dst[(size_t)(n0+yy)*K + k0 + x] = __float2half_rn(t[x][yy]);
}

__global__ void build_emb_kernel(const int* __restrict__ ids,
                                 const float* __restrict__ table){
    int i = blockIdx.x;               // b*SEQ+t
    int id = ids[i];
    const float* src = table + (size_t)id*DM;
    float* dst = g_emb + (size_t)i*DM;
    for (int c = threadIdx.x; c < DM; c += 128) dst[c] = src[c];
}

__global__ void pwq_kernel(const float* __restrict__ wk,
                           const float* __restrict__ q){
    int d = threadIdx.x;              // 512 threads
    float s = 0.f;
    #pragma unroll
    for (int k = 0; k < 64; k++) s += wk[d*64 + k]*q[k];
    g_pwq[d] = s;
}

// ---------------- Phase A: pooling + SSM ----------------
// fused pool + layer-0 xz, split-K: grid (32, BSZ), 256 thr.
__global__ void xzpool_kernel(const float* __restrict__ win, int t, int kprev){
    __shared__ float sc[80];
    __shared__ float xs[DM];
    __shared__ float red4[4][65];
    __shared__ float sinv;
    int b = blockIdx.y;
    int tid = threadIdx.x;            // 256
    int lane = tid & 31, wid = tid >> 5;   // 8 warps
    const float* srow = g_ssmv + ((size_t)kprev*BSZ + b)*DM;
    for (int j = wid; j < TW; j += 8){
        const float* row = nullptr;
        if (j == 0) row = srow;
        else { int tt = t - 64 + j; if (tt >= 0) row = g_emb + ((size_t)b*SEQ + tt)*DM; }
        float s = 0.f;
        if (row) for (int d = lane; d < DM; d += 32) s += row[d]*g_pwq[d];
        for (int o = 16; o; o >>= 1) s += __shfl_xor_sync(0xffffffffu, s, o);
        if (lane == 0) sc[j] = s*0.125f;
    }
    __syncthreads();
    if (wid == 0){
        float v0 = sc[lane];
        float v1 = sc[lane + 32];
        float v2 = (lane == 0) ? sc[64] : -1e30f;
        float m = fmaxf(v0, fmaxf(v1, v2));
        for (int o = 16; o; o >>= 1) m = fmaxf(m, __shfl_xor_sync(0xffffffffu, m, o));
        float e0 = expf(v0 - m), e1 = expf(v1 - m);
        float e2 = (lane == 0) ? expf(v2 - m) : 0.f;
        float s = e0 + e1 + e2;
        for (int o = 16; o; o >>= 1) s += __shfl_xor_sync(0xffffffffu, s, o);
        sc[lane] = e0; sc[lane + 32] = e1;
        if (lane == 0){ sc[64] = e2; sinv = 1.f/s; }
    }
    __syncthreads();
    {
        int j0 = (t >= 63) ? 1 : (64 - t);
        for (int d = tid; d < DM; d += 256){
            float acc = sc[0]*srow[d];
            const float* ebase = g_emb + ((size_t)b*SEQ + (t - 64))*DM + d;
            #pragma unroll 4
            for (int j = j0; j < TW; j++)
                acc += sc[j]*ebase[(size_t)j*DM];
            float v = acc*sinv;
            xs[d] = v;
            if (blockIdx.x == 0) g_sx[b*DM + d] = v;
        }
    }
    __syncthreads();
    {
        int cl = tid & 63, sg = tid >> 6;
        int c = blockIdx.x*64 + cl;
        float s = 0.f;
        int d0 = sg*128;
        #pragma unroll 8
        for (int d = d0; d < d0 + 128; d++) s += xs[d]*win[(size_t)d*2048 + c];
        red4[sg][cl] = s;
        __syncthreads();
        if (tid < 64)
            g_xz[b*2048 + blockIdx.x*64 + tid] =
                red4[0][tid] + red4[1][tid] + red4[2][tid] + red4[3][tid];
    }
}

// xz matvec (layer 1), split-K: grid (32, BSZ), 256 thr = 64 cols x 4 K-segments
__global__ void ssm_xz_kernel(const float* __restrict__ win){
    __shared__ float xs[DM];
    __shared__ float red[4][65];
    int b = blockIdx.y;
    int tid = threadIdx.x;
    int cl = tid & 63, sg = tid >> 6;
    int c = blockIdx.x*64 + cl;                 // 0..2047
    for (int i = tid; i < DM; i += 256) xs[i] = g_sx[b*DM + i];
    __syncthreads();
    float s = 0.f;
    int d0 = sg*128;
    #pragma unroll 8
    for (int d = d0; d < d0 + 128; d++) s += xs[d]*win[(size_t)d*2048 + c];
    red[sg][cl] = s;
    __syncthreads();
    if (tid < 64){
        float t = red[0][tid] + red[1][tid] + red[2][tid] + red[3][tid];
        g_xz[b*2048 + blockIdx.x*64 + tid] = t;
    }
}

// fused dt + B/C projections + selective-scan update, split-K
// grid (16, BSZ), 256 thr = 64 cols x 4 K-segments (256 each)
__global__ void ssm_dbh_kernel(const float* __restrict__ wdt,
                               const float* __restrict__ bdt,
                               const float* __restrict__ wB,
                               const float* __restrict__ wC,
                               const float* __restrict__ Alog,
                               const float* __restrict__ Dw, int l){
    __shared__ float xs[DIN];
    __shared__ float red[4][65];
    __shared__ float redbc[8][33];
    __shared__ float bsm[DST], csm[DST];
    int b = blockIdx.y;
    int tid = threadIdx.x;
    int cl = tid & 63, sg = tid >> 6;
    int c = blockIdx.x*64 + cl;                 // 0..1023
    for (int i = tid; i < DIN; i += 256) xs[i] = g_xz[b*2048 + i];
    __syncthreads();
    {
        float s = (sg == 0) ? bdt[c] : 0.f;
        int d0 = sg*256;
        #pragma unroll 8
        for (int d = d0; d < d0 + 256; d++) s += xs[d]*wdt[(size_t)d*DIN + c];
        red[sg][cl] = s;
    }
    {
        int o = tid & 31, seg = tid >> 5;
        const float* w = (o < 16) ? wB : wC;
        int si = o & 15;
        float p = 0.f;
        int e0 = seg*128;
        #pragma unroll 4
        for (int d = e0; d < e0 + 128; d++) p += xs[d]*w[d*DST + si];
        redbc[seg][o] = p;
    }
    __syncthreads();
    if (tid < 32){
        float t = 0.f;
        #pragma unroll
        for (int q = 0; q < 8; q++) t += redbc[q][tid];
        if (tid < 16) bsm[tid] = t; else csm[tid - 16] = t;
    }
    __syncthreads();
    if (tid < 64){
        float dt = softplusf(red[0][tid] + red[1][tid] + red[2][tid] + red[3][tid]);
        int cc = blockIdx.x*64 + tid;
        float x1 = xs[cc];
        float z  = g_xz[b*2048 + DIN + cc];
        float* hp = g_hst + (((size_t)l*BSZ + b)*DIN + cc)*DST;
        float y = 0.f;
        #pragma unroll
        for (int q = 0; q < DST; q++){
            float Av = -expf(Alog[cc*DST + q]);
            float hv = expf(dt*Av)*hp[q] + dt*bsm[q]*x1;
            hp[q] = hv;
            y += hv*csm[q];
        }
        y += Dw[cc]*x1;
        y *= siluf(z);
        g_y[b*DIN + cc] = y;
    }
}

// xup matvec, split-K: grid (16, BSZ), 256 thr = 32 cols x 8 K-segments (128 each)
__global__ void ssm_xup_kernel(const float* __restrict__ wout, int k, int last){
    __shared__ float ys[DIN];
    __shared__ float red[8][33];
    int b = blockIdx.y;
    int tid = threadIdx.x;
    int cl = tid & 31, sg = tid >> 5;
    int c = blockIdx.x*32 + cl;                 // 0..511
    for (int i = tid; i < DIN; i += 256) ys[i] = g_y[b*DIN + i];
    __syncthreads();
    float s = 0.f;
    int d0 = sg*128;
    #pragma unroll 8
    for (int d = d0; d < d0 + 128; d++) s += ys[d]*wout[(size_t)d*DM + c];
    red[sg][cl] = s;
    __syncthreads();
    if (tid < 32){
        float t = 0.f;
        #pragma unroll
        for (int q = 0; q < 8; q++) t += red[q][tid];
        int cc = blockIdx.x*32 + tid;
        float nv = g_sx[b*DM + cc] + t;
        g_sx[b*DM + cc] = nv;
        if (last) g_ssmv[((size_t)k*BSZ + b)*DM + cc] = nv;
    }
}

// ---------------- Phase B: batched transformer ----------------
// LayerNorm; fp32 in (strided), half out
__global__ void ln_kernel(const float* __restrict__ in, long long ldi,
                          __half* __restrict__ out, long long ldo,
                          const float* __restrict__ gw,
                          const float* __restrict__ bw){
    long long r = blockIdx.x;
    const float* x = in + r*ldi;
    int tid = threadIdx.x;             // 256
    float v0 = x[tid], v1 = x[tid + 256];
    float s = v0 + v1, q = v0*v0 + v1*v1;
    __shared__ float ss[8], sq[8];
    for (int o = 16; o; o >>= 1){
        s += __shfl_xor_sync(0xffffffffu, s, o);
        q += __shfl_xor_sync(0xffffffffu, q, o);
    }
    if ((tid & 31) == 0){ ss[tid >> 5] = s; sq[tid >> 5] = q; }
    __syncthreads();
    if (tid < 8){
        s = ss[tid]; q = sq[tid];
        for (int o = 4; o; o >>= 1){
            s += __shfl_xor_sync(0xffu, s, o);
            q += __shfl_xor_sync(0xffu, q, o);
        }
        if (tid == 0){ ss[0] = s; sq[0] = q; }
    }
    __syncthreads();
    float mu  = ss[0]*(1.f/512.f);
    float var = sq[0]*(1.f/512.f) - mu*mu;
    float inv = rsqrtf(var + 1e-5f);
    __half* o = out + r*ldo;
    o[tid]       = __float2half_rn((v0 - mu)*inv*gw[tid] + bw[tid]);
    o[tid + 256] = __float2half_rn((v1 - mu)*inv*gw[tid + 256] + bw[tid + 256]);
}

// LN over gathered unique rows (replaces build_uniq + ln)
__global__ void ln_uniq_kernel(__half* __restrict__ out,
                               const float* __restrict__ gw,
                               const float* __restrict__ bw){
    int u = blockIdx.x;                // 0..UPAD-1
    const float* x = gatherU(u);
    int tid = threadIdx.x;             // 256
    float v0 = x ? x[tid] : 0.f;
    float v1 = x ? x[tid + 256] : 0.f;
    float s = v0 + v1, q = v0*v0 + v1*v1;
    __shared__ float ss[8], sq[8];
    for (int o = 16; o; o >>= 1){
        s += __shfl_xor_sync(0xffffffffu, s, o);
        q += __shfl_xor_sync(0xffffffffu, q, o);
    }
    if ((tid & 31) == 0){ ss[tid >> 5] = s; sq[tid >> 5] = q; }
    __syncthreads();
    if (tid < 8){
        s = ss[tid]; q = sq[tid];
        for (int o = 4; o; o >>= 1){
            s += __shfl_xor_sync(0xffu, s, o);
            q += __shfl_xor_sync(0xffu, q, o);
        }
        if (tid == 0){ ss[0] = s; sq[0] = q; }
    }
    __syncthreads();
    float mu  = ss[0]*(1.f/512.f);
    float var = sq[0]*(1.f/512.f) - mu*mu;
    float inv = rsqrtf(var + 1e-5f);
    __half* o = out + (size_t)u*DM;
    o[tid]       = __float2half_rn((v0 - mu)*inv*gw[tid] + bw[tid]);
    o[tid + 256] = __float2half_rn((v1 - mu)*inv*gw[tid + 256] + bw[tid + 256]);
}

// -------- pipelined fp16 tensor-core GEMM (m16n8k16 + ldmatrix) --------
// batched via blockIdx.z with element strides abz/bbz/cbz (0 for unbatched).
#define LDHW 72            // halves per smem row (64 + 8 pad); 144 B
#define TILEH (128*LDHW)   // 9216 halves = 18432 B per tile

template<int ACT, bool RESID, bool HASBIAS, bool SWAPXY, bool OUTH, bool GX>
__global__ __launch_bounds__(128, 2)
void hgemm(const __half* __restrict__ A, long long lda,
           const __half* __restrict__ B, long long ldb,
           void* __restrict__ Cv, long long ldc,
           const float* __restrict__ bias, int K,
           long long abz, long long bbz, long long cbz){
    extern __shared__ __half sh[];
    __half* As = sh;                 // [2][TILEH]
    __half* Bs = sh + 2*TILEH;       // [2][TILEH]

    int bz = blockIdx.z;
    A += (long long)bz*abz;
    B += (long long)bz*bbz;
    if (OUTH) Cv = (void*)((__half*)Cv + (long long)bz*cbz);
    else      Cv = (void*)((float*)Cv + (long long)bz*cbz);

    long long bm = (long long)(SWAPXY ? blockIdx.x : blockIdx.y)*128;
    long long bn = (long long)(SWAPXY ? blockIdx.y : blockIdx.x)*128;
    int tid = threadIdx.x;
    int lane = tid & 31, wid = tid >> 5;
    int g = lane >> 2, r = lane & 3;
    int wm = (wid >> 1)*64, wn = (wid & 1)*64;

    int lrow = tid >> 3, lcc = tid & 7;
    const __half* Abase = A + (bm + lrow)*lda + lcc*8;
    const __half* Bbase = B + (bn + lrow)*ldb + lcc*8;
    unsigned aS = (unsigned)__cvta_generic_to_shared(As) + (lrow*144u + lcc*16u);
    unsigned bS = (unsigned)__cvta_generic_to_shared(Bs) + (lrow*144u + lcc*16u);

    int lr = lane & 15;
    unsigned kh = (unsigned)((lane >> 4)*16);
    unsigned aLm = (unsigned)__cvta_generic_to_shared(As) + (unsigned)((wm + lr)*144) + kh;
    unsigned bLm = (unsigned)__cvta_generic_to_shared(Bs) + (unsigned)((wn + lr)*144) + kh;

    float acc[4][8][4];
    #pragma unroll
    for (int i = 0; i < 4; i++)
        #pragma unroll
        for (int j = 0; j < 8; j++)
            #pragma unroll
            for (int q = 0; q < 4; q++) acc[i][j][q] = 0.f;

    int nkt = K >> 6;

    #pragma unroll
    for (int i = 0; i < 8; i++){
        cpa16(aS + i*16u*144u, Abase + (size_t)16*i*lda);
        cpa16(bS + i*16u*144u, Bbase + (size_t)16*i*ldb);
    }
    CP_COMMIT();

    for (int kt = 0; kt < nkt; kt++){
        int cur = kt & 1;
        if (kt + 1 < nkt){
            unsigned so = (cur ^ 1) ? (unsigned)(TILEH*2) : 0u;
            long long ko = (long long)(kt + 1)*64;
            #pragma unroll
            for (int i = 0; i < 8; i++){
                cpa16(aS + so + i*16u*144u, Abase + (size_t)16*i*lda + ko);
                cpa16(bS + so + i*16u*144u, Bbase + (size_t)16*i*ldb + ko);
            }
            CP_COMMIT();
            CP_WAIT1();
        } else {
            CP_WAIT0();
        }
        __syncthreads();

        unsigned coff = (unsigned)cur*(TILEH*2);
        #pragma unroll
        for (int ks = 0; ks < 4; ks++){
            unsigned kso = coff + (unsigned)ks*32u;
            unsigned af[4][4], bf[8][2];
            #pragma unroll
            for (int mt = 0; mt < 4; mt++)
                ldsm4(af[mt][0], af[mt][1], af[mt][2], af[mt][3],
                      aLm + kso + (unsigned)mt*2304u);
            #pragma unroll
            for (int p = 0; p < 4; p++)
                ldsm4(bf[2*p][0], bf[2*p+1][0], bf[2*p][1], bf[2*p+1][1],
                      bLm + kso + (unsigned)p*2304u);
            #pragma unroll
            for (int mt = 0; mt < 4; mt++)
                #pragma unroll
                for (int nt = 0; nt < 8; nt++)
                    mma_f16(acc[mt][nt], af[mt], bf[nt]);
        }
        __syncthreads();
    }

    #pragma unroll
    for (int mt = 0; mt < 4; mt++){
        const float* gx0 = nullptr;
        const float* gx1 = nullptr;
        if (GX){
            int rr0 = (int)(bm + wm) + mt*16 + g;
            gx0 = gatherX(rr0);
            gx1 = gatherX(rr0 + 8);
        }
        #pragma unroll
        for (int nt = 0; nt < 8; nt++){
            long long row0 = bm + wm + mt*16 + g;
            long long col  = bn + wn + nt*8 + r*2;
            float b0 = 0.f, b1 = 0.f;
            if (HASBIAS){ b0 = bias[col]; b1 = bias[col+1]; }
            float v00 = acc[mt][nt][0] + b0, v01 = acc[mt][nt][1] + b1;
            float v10 = acc[mt][nt][2] + b0, v11 = acc[mt][nt][3] + b1;
            if (ACT == 1){ v00 = geluf(v00); v01 = geluf(v01);
                           v10 = geluf(v10); v11 = geluf(v11); }
            if (GX){
                if (gx0){ v00 += gx0[col]; v01 += gx0[col+1]; }
                if (gx1){ v10 += gx1[col]; v11 += gx1[col+1]; }
            }
            if (OUTH){
                __half* C = (__half*)Cv;
                *(__half2*)(C + row0*ldc + col)     = __floats2half2_rn(v00, v01);
                *(__half2*)(C + (row0+8)*ldc + col) = __floats2half2_rn(v10, v11);
            } else {
                float* C = (float*)Cv;
                float* c0 = C + row0*ldc + col;
                float* c1 = C + (row0+8)*ldc + col;
                if (RESID){
                    float2 r0 = *(float2*)c0, r1 = *(float2*)c1;
                    v00 += r0.x; v01 += r0.y; v10 += r1.x; v11 += r1.y;
                }
                *(float2*)c0 = make_float2(v00, v01);
                *(float2*)c1 = make_float2(v10, v11);
            }
        }
    }
}

// full causal attention (layer 0): per (window, head); half2 smem K/V.
__global__ __launch_bounds__(256)
void attn_full_kernel(const __half* __restrict__ QKVU, __half* __restrict__ O){
    int w = blockIdx.x, h = blockIdx.y;
    int b = w >> 8, t = w & 255;
    __shared__ __half2 Ksh[TW*33];
    __shared__ __half2 Vsh[TW*33];
    __shared__ float qs[8][64];
    __shared__ float ps[8][68];
    __shared__ int us[TW];
    int tid = threadIdx.x;
    int lane = tid & 31, wid = tid >> 5;
    if (tid < TW){
        int j = tid, u;
        if (j == 0){
            int k = (t >= 17) ? ((t-1) >> 4) : 0;
            u = k ? (1025 + (k-1)*4 + b) : 0;
        } else {
            int tt = t - 64 + j;
            u = (tt >= 0) ? (1 + b*256 + tt) : 0;
        }
        us[j] = u;
    }
    __syncthreads();
    for (int idx = tid; idx < TW*32; idx += 256){
        int j = idx >> 5, d2 = idx & 31;
        const __half* base = QKVU + (size_t)us[j]*1536 + h*64;
        Ksh[j*33 + d2] = ((const __half2*)(base + 512))[d2];
        Vsh[j*33 + d2] = ((const __half2*)(base + 1024))[d2];
    }
    __syncthreads();
    for (int j = wid; j < TW; j += 8){
        const __half* qb = QKVU + (size_t)us[j]*1536 + h*64;
        qs[wid][lane]      = __half2float(qb[lane]);
        qs[wid][lane + 32] = __half2float(qb[lane + 32]);
        __syncwarp();
        int nk = j + 1;
        float sv[3];
        float pmax = -1e30f;
        #pragma unroll
        for (int r = 0; r < 3; r++){
            int k = lane + r*32;
            float s = -1e30f;
            if (k < nk){
                s = 0.f;
                const __half2* kr = &Ksh[k*33];
                #pragma unroll
                for (int d2 = 0; d2 < 32; d2++){
                    float2 f = __half22float2(kr[d2]);
                    s += qs[wid][2*d2]*f.x + qs[wid][2*d2+1]*f.y;
                }
                s *= 0.125f;
            }
            sv[r] = s;
            pmax = fmaxf(pmax, s);
        }
        for (int o = 16; o; o >>= 1)
            pmax = fmaxf(pmax, __shfl_xor_sync(0xffffffffu, pmax, o));
        float psum = 0.f;
        #pragma unroll
        for (int r = 0; r < 3; r++){
            int k = lane + r*32;
            float e = (k < nk) ? expf(sv[r] - pmax) : 0.f;
            if (k < nk) ps[wid][k] = e;
            psum += e;
        }
        for (int o = 16; o; o >>= 1)
            psum += __shfl_xor_sync(0xffffffffu, psum, o);
        float inv = 1.f/psum;
        __syncwarp();
        {
            float a0 = 0.f, a1 = 0.f;
            for (int k = 0; k < nk; k++){
                float p = ps[wid][k];
                float2 f = __half22float2(Vsh[k*33 + lane]);
                a0 += p*f.x;
                a1 += p*f.y;
            }
            __half2* orow = (__half2*)(O + (size_t)(w*TW + j)*DM + h*64);
            orow[lane] = __floats2half2_rn(a0*inv, a1*inv);
        }
        __syncwarp();
    }
}

// layer-1 attention mix: scores from vqH (= xn_last @ M2^T), softmax,
// mixed rows sbar (half out)
#define AMIX_SMEM (TW*DM*2 + NH*DM*4 + NH*68*4)
__global__ void attn_mix_kernel(){
    extern __shared__ char sm[];
    __half* xn = (__half*)sm;                        // [65][512]
    float* vsh = (float*)(sm + TW*DM*2);             // [8][512]
    float* sc  = vsh + NH*DM;                        // [8][68]
    int w = blockIdx.x;
    int tid = threadIdx.x;             // 256
    int lane = tid & 31, wid = tid >> 5;
    const uint4* src = (const uint4*)(g_XN + (size_t)w*TW*DM);
    for (int i = tid; i < TW*DM/8; i += 256) ((uint4*)xn)[i] = src[i];
    const __half* vsrc = g_vqH + (size_t)w*NH*DM;
    for (int i = tid; i < NH*DM; i += 256) vsh[i] = __half2float(vsrc[i]);
    __syncthreads();
    {
        int h = wid;
        const float* v = vsh + h*DM;
        for (int j = 0; j < TW; j++){
            const __half2* xr = (const __half2*)(xn + j*DM);
            float s = 0.f;
            #pragma unroll
            for (int i = lane; i < 256; i += 32){
                __half2 hv = xr[i];
                s += __low2float(hv)*v[2*i] + __high2float(hv)*v[2*i+1];
            }
            for (int o = 16; o; o >>= 1) s += __shfl_xor_sync(0xffffffffu, s, o);
            if (lane == 0) sc[h*68 + j] = s*0.125f;
        }
        __syncwarp();
        float v0 = sc[h*68 + lane];
        float v1 = sc[h*68 + lane + 32];
        float v2 = (lane == 0) ? sc[h*68 + 64] : -1e30f;
        float m = fmaxf(v0, fmaxf(v1, v2));
        for (int o = 16; o; o >>= 1) m = fmaxf(m, __shfl_xor_sync(0xffffffffu, m, o));
        float e0 = expf(v0 - m), e1 = expf(v1 - m);
        float e2 = (lane == 0) ? expf(v2 - m) : 0.f;
        float su = e0 + e1 + e2;
        for (int o = 16; o; o >>= 1) su += __shfl_xor_sync(0xffffffffu, su, o);
        float inv = 1.f/su;
        sc[h*68 + lane] = e0*inv;
        sc[h*68 + lane + 32] = e1*inv;
        if (lane == 0) sc[h*68 + 64] = e2*inv;
    }
    __syncthreads();
    __half* outp = g_sbarH + (size_t)w*NH*DM;
    #pragma unroll 1
    for (int h = 0; h < NH; h++){
        float a0 = 0.f, a1 = 0.f;
        const float* aw = sc + h*68;
        for (int j = 0; j < TW; j++){
            float a = aw[j];
            __half2 hv = *(const __half2*)(xn + j*DM + tid*2);
            a0 += a*__low2float(hv);
            a1 += a*__high2float(hv);
        }
        *(__half2*)(outp + h*DM + tid*2) = __floats2half2_rn(a0, a1);
    }
}

// ---------------- host ----------------
template<int ACT, bool RESID, bool HASBIAS, bool SWAPXY, bool OUTH, bool GX>
static void launch_hgemm(dim3 grid, const __half* A, long long lda,
                         const __half* B, long long ldb,
                         void* C, long long ldc,
                         const float* bias, int K,
                         long long abz = 0, long long bbz = 0, long long cbz = 0){
    int smem = 4*TILEH*2;       // 73728 B
    cudaFuncSetAttribute(hgemm<ACT,RESID,HASBIAS,SWAPXY,OUTH,GX>,
                         cudaFuncAttributeMaxDynamicSharedMemorySize, smem);
    hgemm<ACT,RESID,HASBIAS,SWAPXY,OUTH,GX><<<grid, 128, smem>>>(
        A, lda, B, ldb, C, ldc, bias, K, abz, bbz, cbz);
}

extern "C" void kernel_launch(void* const* d_in, const int* in_sizes, int n_in,
                              void* d_out, int out_size){
    const int*   input_ids = (const int*)  d_in[0];
    const float* embedding = (const float*)d_in[1];
    const float* ln1_g = (const float*)d_in[2];
    const float* ln1_b = (const float*)d_in[3];
    const float* wqkv  = (const float*)d_in[4];
    const float* wo    = (const float*)d_in[5];
    const float* ln2_g = (const float*)d_in[6];
    const float* ln2_b = (const float*)d_in[7];
    const float* w1    = (const float*)d_in[8];
    const float* b1    = (const float*)d_in[9];
    const float* w2    = (const float*)d_in[10];
    const float* b2    = (const float*)d_in[11];
    const float* lnf_g = (const float*)d_in[12];
    const float* lnf_b = (const float*)d_in[13];
    const float* pool_q  = (const float*)d_in[14];
    const float* pool_wk = (const float*)d_in[15];
    const float* ssm_win = (const float*)d_in[16];
    const float* ssm_wdt = (const float*)d_in[17];
    const float* ssm_bdt = (const float*)d_in[18];
    const float* ssm_Alog= (const float*)d_in[19];
    const float* ssm_wB  = (const float*)d_in[20];
    const float* ssm_wC  = (const float*)d_in[21];
    const float* ssm_D   = (const float*)d_in[22];
    const float* ssm_wout= (const float*)d_in[23];
    float* out = (float*)d_out;

    float *pX;
    __half *pQKVU, *pUN, *pXN, *pW, *pO, *pXL, *pHL, *pFL;
    __half *pWqkvT, *pWoT, *pW1T, *pW2T, *pEmbH;
    __half *pWqkvH1, *pM2T, *pM3T, *pVqH, *pSbarH;
    cudaGetSymbolAddress((void**)&pX,  g_X);
    cudaGetSymbolAddress((void**)&pQKVU, g_QKVU);
    cudaGetSymbolAddress((void**)&pUN, g_UN);
    cudaGetSymbolAddress((void**)&pXN, g_XN);
    cudaGetSymbolAddress((void**)&pW,  g_wide);
    cudaGetSymbolAddress((void**)&pO,  g_O);
    cudaGetSymbolAddress((void**)&pXL, g_XL);
    cudaGetSymbolAddress((void**)&pHL, g_HL);
    cudaGetSymbolAddress((void**)&pFL, g_FL);
    cudaGetSymbolAddress((void**)&pWqkvT, g_wqkvT);
    cudaGetSymbolAddress((void**)&pWoT, g_woT);
    cudaGetSymbolAddress((void**)&pW1T, g_w1T);
    cudaGetSymbolAddress((void**)&pW2T, g_w2T);
    cudaGetSymbolAddress((void**)&pEmbH, g_embh);
    cudaGetSymbolAddress((void**)&pWqkvH1, g_wqkvH1);
    cudaGetSymbolAddress((void**)&pM2T, g_M2T);
    cudaGetSymbolAddress((void**)&pM3T, g_M3T);
    cudaGetSymbolAddress((void**)&pVqH, g_vqH);
    cudaGetSymbolAddress((void**)&pSbarH, g_sbarH);

    init_zero_kernel<<<512, 256>>>();
    build_emb_kernel<<<BSZ*SEQ, 128>>>(input_ids, embedding);
    pwq_kernel<<<1, 512>>>(pool_wk, pool_q);

    // weight prep: transpose [K,N]->[N,K] half; embedding -> half; raw wqkv1 -> half
    dim3 tb(32, 8);
    for (int l = 0; l < 2; l++){
        transpose_half_kernel<<<dim3(1536/32, DM/32), tb>>>(
            wqkv + (size_t)l*DM*1536, pWqkvT + (size_t)l*1536*DM, DM, 1536);
        transpose_half_kernel<<<dim3(DM/32, DM/32), tb>>>(
            wo + (size_t)l*DM*DM, pWoT + (size_t)l*DM*DM, DM, DM);
        transpose_half_kernel<<<dim3(DFFN/32, DM/32), tb>>>(
            w1 + (size_t)l*DM*DFFN, pW1T + (size_t)l*DFFN*DM, DM, DFFN);
        transpose_half_kernel<<<dim3(DM/32, DFFN/32), tb>>>(
            w2 + (size_t)l*DFFN*DM, pW2T + (size_t)l*DM*DFFN, DFFN, DM);
    }
    tohalf_kernel<<<4096, 256>>>(embedding, pEmbH, VOC*DM);
    tohalf_kernel<<<512, 256>>>(wqkv + (size_t)DM*1536, pWqkvH1, DM*1536);

    // composite matrices for folded layer-1 attention (batched over 8 heads):
    // M2T[h*512+d][e] = sum_c Wk1[d][c] Wq1[e][c]      (scores)
    launch_hgemm<0,false,false,false,true,false>(dim3(4, 4, 8),
        pWqkvH1 + 512, 1536, pWqkvH1, 1536, pM2T, 512, nullptr, 64,
        64, 64, (long long)512*512);
    // M3T[e][h*512+d] = sum_c Wo1T[e][h*64+c] Wv1[d][c]  (value->resid)
    launch_hgemm<0,false,false,false,true,false>(dim3(4, 4, 8),
        pWoT + (size_t)DM*DM, 512, pWqkvH1 + 1024, 1536, pM3T, 4096, nullptr, 64,
        64, 64, 512);

    // ---- Phase A: 15 sequential SSM writes (split-K kernels) ----
    for (int k = 1; k <= 15; k++){
        int t = 16*k;
        for (int l = 0; l < 2; l++){
            if (l == 0)
                xzpool_kernel<<<dim3(32, BSZ), 256>>>(ssm_win, t, k-1);
            else
                ssm_xz_kernel<<<dim3(32, BSZ), 256>>>(ssm_win + (size_t)DM*2*DIN);
            ssm_dbh_kernel<<<dim3(16, BSZ), 256>>>(ssm_wdt + (size_t)l*DIN*DIN,
                                                   ssm_bdt + (size_t)l*DIN,
                                                   ssm_wB + (size_t)l*DIN*DST,
                                                   ssm_wC + (size_t)l*DIN*DST,
                                                   ssm_Alog + (size_t)l*DIN*DST,
                                                   ssm_D + (size_t)l*DIN, l);
            ssm_xup_kernel<<<dim3(16, BSZ), 256>>>(ssm_wout + (size_t)l*DIN*DM, k, l);
        }
    }

    // ---- Phase B ----
    ln_uniq_kernel<<<UPAD, 256>>>(pUN, ln1_g, ln1_b);
    launch_hgemm<0,false,false,false,true,false>(dim3(1536/128, UPAD/128),
        pUN, DM, pWqkvT, DM, pQKVU, 1536, nullptr, DM);

    attn_full_kernel<<<dim3(NWIN, NH), 256>>>(pQKVU, pO);
    launch_hgemm<0,false,false,false,false,true>(dim3(DM/128, NROWS/128),
        pO, DM, pWoT, DM, pX, DM, nullptr, DM);
    ln_kernel<<<NROWS, 256>>>(pX, DM, pXN, DM, ln2_g, ln2_b);
    launch_hgemm<1,false,true,false,true,false>(dim3(DFFN/128, NROWS/128),
        pXN, DM, pW1T, DM, pW, DFFN, b1, DM);
    launch_hgemm<0,true,true,false,false,false>(dim3(DM/128, NROWS/128),
        pW, DFFN, pW2T, DFFN, pX, DM, b2, DFFN);

    // layer 1: folded factored attention (no Q/KV GEMMs, no vq/vo matvecs)
    ln_kernel<<<NROWS, 256>>>(pX, DM, pXN, DM, ln1_g + DM, ln1_b + DM);
    launch_hgemm<0,false,false,false,true,false>(dim3(4096/128, NWIN/128),
        pXN + (size_t)64*DM, (long long)TW*DM, pM2T, DM, pVqH, 4096, nullptr, DM);
    cudaFuncSetAttribute(attn_mix_kernel,
                         cudaFuncAttributeMaxDynamicSharedMemorySize, AMIX_SMEM);
    attn_mix_kernel<<<NWIN, 256, AMIX_SMEM>>>();
    launch_hgemm<0,true,false,false,false,false>(dim3(DM/128, NWIN/128),
        pSbarH, 4096, pM3T, 4096, pX + (size_t)64*DM, (long long)TW*DM,
        nullptr, 4096);
    ln_kernel<<<NWIN, 256>>>(pX + (size_t)64*DM, (long long)TW*DM, pXL, DM,
                             ln2_g + DM, ln2_b + DM);
    launch_hgemm<1,false,true,false,true,false>(dim3(DFFN/128, NWIN/128),
        pXL, DM, pW1T + (size_t)DFFN*DM, DM, pHL, DFFN, b1 + DFFN, DM);
    launch_hgemm<0,true,true,false,false,false>(dim3(DM/128, NWIN/128),
        pHL, DFFN, pW2T + (size_t)DM*DFFN, DFFN, pX + (size_t)64*DM, (long long)TW*DM,
        b2 + DM, DFFN);

    // final LN (last rows) + tied logits
    ln_kernel<<<NWIN, 256>>>(pX + (size_t)64*DM, (long long)TW*DM, pFL, DM,
                             lnf_g, lnf_b);
    launch_hgemm<0,false,false,true,false,false>(dim3(NWIN/128, VOC/128),
        pFL, DM, pEmbH, DM, out, VOC, nullptr, DM);
}